// round 13
// baseline (speedup 1.0000x reference)
#include <cuda_runtime.h>
#include <cuda_bf16.h>
#include <float.h>

#define NTOK   4096
#define DMODEL 320
#define HEADS  8
#define DH     40
#define NPHASE 3
#define KTILE  32
#define QBLK   64
#define UT     8          // 8 tiles x 32 keys = 256-key uniform units
#define MAXU   1152
#define MAXSPL 16

typedef unsigned long long ull;

#define FMA2(d, a, b, c) \
    asm("fma.rn.f32x2 %0, %1, %2, %3;" : "=l"(d) : "l"(a), "l"(b), "l"(c))
#define MUL2(d, a, b) \
    asm("mul.rn.f32x2 %0, %1, %2;" : "=l"(d) : "l"(a), "l"(b))
#define PACK2(d, lo, hi) \
    asm("mov.b64 %0, {%1, %2};" : "=l"(d) : "f"(lo), "f"(hi))
#define UNPACK2(lo, hi, v) \
    asm("mov.b64 {%0, %1}, %2;" : "=f"(lo), "=f"(hi) : "l"(v))

#define LDSM_X4(r0, r1, r2, r3, addr) \
    asm volatile("ldmatrix.sync.aligned.m8n8.x4.shared.b16 {%0,%1,%2,%3}, [%4];" \
        : "=r"(r0), "=r"(r1), "=r"(r2), "=r"(r3) : "r"(addr))
#define LDSM_X4T(r0, r1, r2, r3, addr) \
    asm volatile("ldmatrix.sync.aligned.m8n8.x4.trans.shared.b16 {%0,%1,%2,%3}, [%4];" \
        : "=r"(r0), "=r"(r1), "=r"(r2), "=r"(r3) : "r"(addr))
#define MMA_BF16(c, a, b) \
    asm volatile("mma.sync.aligned.m16n8k16.row.col.f32.bf16.bf16.f32 " \
        "{%0,%1,%2,%3}, {%4,%5,%6,%7}, {%8,%9}, {%0,%1,%2,%3};" \
        : "+f"((c)[0]), "+f"((c)[1]), "+f"((c)[2]), "+f"((c)[3]) \
        : "r"((a)[0]), "r"((a)[1]), "r"((a)[2]), "r"((a)[3]), \
          "r"((b)[0]), "r"((b)[1]))

#define CP_ASYNC16(dst, src) \
    asm volatile("cp.async.cg.shared.global [%0], [%1], 16;" :: "r"(dst), "l"(src))
#define CP_COMMIT() asm volatile("cp.async.commit_group;" ::: "memory")
#define CP_WAIT1()  asm volatile("cp.async.wait_group 1;" ::: "memory")
#define CP_WAIT0()  asm volatile("cp.async.wait_group 0;" ::: "memory")

// ---------------- scratch (__device__ globals; no allocation allowed) -------
__device__ float g_q[HEADS * NTOK * DH];
__device__ float g_k[HEADS * NTOK * DH];
__device__ float g_v[HEADS * NTOK * DH];
__device__ float g_o[NTOK * DMODEL];
__device__ unsigned g_mb[NPHASE * (NTOK / 32)];

// planning data
__device__ int g_grp_cnt[8], g_grp_off[8];
__device__ int g_qidx[NTOK];
__device__ int g_kcnt[8];
__device__ int g_kidx[8][NTOK];
__device__ int g_nsplit[8];
__device__ int g_u_sig[MAXU], g_u_qoff[MAXU], g_u_qend[MAXU];
__device__ int g_u_t0[MAXU], g_u_t1[MAXU], g_u_spl[MAXU];
__device__ int g_nunits;

// compacted K/V: [sig-1][head][jc][40]
__device__ float g_kc[7 * HEADS * NTOK * DH];
__device__ float g_vc[7 * HEADS * NTOK * DH];
__device__ float g_meanv[HEADS * DH];
__device__ float g_mvpart[16][HEADS * DH];

// split partials: indexed [spl][head][ql]
__device__ float g_pacc[MAXSPL * HEADS * NTOK * DH];
__device__ float g_pm[MAXSPL * HEADS * NTOK];
__device__ float g_pl[MAXSPL * HEADS * NTOK];

__device__ __forceinline__ float ex2(float x) {
    float r;
    asm("ex2.approx.ftz.f32 %0, %1;" : "=f"(r) : "f"(x));
    return r;
}
__device__ __forceinline__ unsigned s2u(const void* p) {
    return (unsigned)__cvta_generic_to_shared(p);
}

// ---------------------------------------------------------------------------
// Pack guidance mask into bitwords (parallel; proven R9 version)
// ---------------------------------------------------------------------------
__global__ void mask_kernel(const float* __restrict__ gm) {
    int w = blockIdx.x * blockDim.x + threadIdx.x;
    if (w < NPHASE * (NTOK / 32)) {
        unsigned bits = 0;
        #pragma unroll 8
        for (int b = 0; b < 32; b++)
            if (gm[w * 32 + b] != 0.0f) bits |= (1u << b);
        g_mb[w] = bits;
    }
}

// ---------------------------------------------------------------------------
// Plan kernel (proven R9 structure; KTILE=32 / UT=8 keeps identical 256-key
// units and split counts)
// ---------------------------------------------------------------------------
__global__ __launch_bounds__(256) void plan_kernel() {
    __shared__ int sq[8][256];
    __shared__ int sk[8][256];
    __shared__ int base_q[8];
    const int t = threadIdx.x;

    unsigned bits_arr[16];
    int cq[8], ck[8];
    #pragma unroll
    for (int s = 0; s < 8; s++) { cq[s] = 0; ck[s] = 0; }

    for (int u = 0; u < 16; u++) {
        int i = t * 16 + u;
        unsigned b = 0;
        #pragma unroll
        for (int p = 0; p < NPHASE; p++)
            b |= ((g_mb[p * 128 + (i >> 5)] >> (i & 31)) & 1u) << p;
        bits_arr[u] = b;
        cq[b]++;
        #pragma unroll
        for (int s = 1; s < 8; s++)
            if (b & (unsigned)s) ck[s]++;
    }
    #pragma unroll
    for (int s = 0; s < 8; s++) { sq[s][t] = cq[s]; sk[s][t] = ck[s]; }
    __syncthreads();

    for (int g = 0; g < 15; g++) {
        int* arr = (g < 8) ? sq[g] : sk[g - 7];
        for (int off = 1; off < 256; off <<= 1) {
            int u = (t >= off) ? arr[t - off] : 0;
            __syncthreads();
            arr[t] += u;
            __syncthreads();
        }
    }

    if (t == 0) {
        int acc = 0;
        for (int s = 0; s < 8; s++) {
            base_q[s] = acc;
            g_grp_off[s] = acc;
            int tot = sq[s][255];
            g_grp_cnt[s] = tot;
            acc += tot;
        }
        int nu = 0;
        for (int s = 1; s < 8; s++) {
            int kc = sk[s][255];
            g_kcnt[s] = kc;
            int cnt = sq[s][255], off = base_q[s];
            int tiles = (kc + KTILE - 1) / KTILE;
            int ns = (tiles + UT - 1) / UT;
            g_nsplit[s] = ns;
            for (int b = 0; b * QBLK < cnt; b++) {
                for (int sp = 0; sp < ns; sp++) {
                    g_u_sig[nu] = s;
                    g_u_qoff[nu] = off + b * QBLK;
                    g_u_qend[nu] = off + cnt;
                    g_u_t0[nu] = sp * UT * KTILE;
                    int t1 = (sp + 1) * UT * KTILE;
                    g_u_t1[nu] = (t1 < kc) ? t1 : kc;
                    g_u_spl[nu] = sp;
                    nu++;
                }
            }
        }
        g_nunits = nu;
    }
    __syncthreads();

    int qcur[8], kcur[8];
    #pragma unroll
    for (int s = 0; s < 8; s++) {
        qcur[s] = base_q[s] + sq[s][t] - cq[s];
        kcur[s] = sk[s][t] - ck[s];
    }
    for (int u = 0; u < 16; u++) {
        int i = t * 16 + u;
        unsigned b = bits_arr[u];
        g_qidx[qcur[b]++] = i;
        #pragma unroll
        for (int s = 1; s < 8; s++)
            if (b & (unsigned)s) g_kidx[s][kcur[s]++] = i;
    }
}

// ---------------------------------------------------------------------------
// QKV projection via bf16 split-precision MMA (proven R10 version).
// ---------------------------------------------------------------------------
#define SKA 40
#define SNB 72

__global__ __launch_bounds__(256) void qkv_gemm(
    const float* __restrict__ X,
    const float* __restrict__ Wq, const float* __restrict__ Wk,
    const float* __restrict__ Wv)
{
    const float* W = (blockIdx.z == 0) ? Wq : (blockIdx.z == 1) ? Wk : Wv;
    float* Dst = (blockIdx.z == 0) ? g_q : (blockIdx.z == 1) ? g_k : g_v;

    __shared__ __nv_bfloat16 Ah[128 * SKA], Al[128 * SKA];
    __shared__ __nv_bfloat16 Bh[32 * SNB],  Bl[32 * SNB];

    const int tid  = threadIdx.x;
    const int lane = tid & 31;
    const int wid  = tid >> 5;
    const int warp_m = wid >> 1;
    const int warp_n = wid & 1;
    const int m0 = blockIdx.y * 128;
    const int n0 = blockIdx.x * 64;
    const int quad = lane >> 3, rr = lane & 7;

    float c[2][4][4];
    #pragma unroll
    for (int mf = 0; mf < 2; mf++)
        #pragma unroll
        for (int nf = 0; nf < 4; nf++)
            #pragma unroll
            for (int r = 0; r < 4; r++) c[mf][nf][r] = 0.0f;

    const int arow = tid >> 1, ahalf = (tid & 1) * 16;
    const int brow = tid >> 3, bcol = (tid & 7) * 8;

    unsigned aAh[2], aAl[2];
    #pragma unroll
    for (int mf = 0; mf < 2; mf++) {
        int mrow = warp_m * 32 + mf * 16 + (quad & 1) * 8 + rr;
        int kcol = (quad >> 1) * 8;
        aAh[mf] = s2u(&Ah[mrow * SKA + kcol]);
        aAl[mf] = s2u(&Al[mrow * SKA + kcol]);
    }
    unsigned aBh[2], aBl[2];
    #pragma unroll
    for (int nf2 = 0; nf2 < 2; nf2++) {
        int krow = (quad & 1) * 8 + rr;
        int ncol = warp_n * 32 + nf2 * 16 + (quad >> 1) * 8;
        aBh[nf2] = s2u(&Bh[krow * SNB + ncol]);
        aBl[nf2] = s2u(&Bl[krow * SNB + ncol]);
    }

    for (int k0 = 0; k0 < DMODEL; k0 += 32) {
        float4 av[4], wv[2];
        const float4* asrc = (const float4*)(X + (size_t)(m0 + arow) * DMODEL + k0 + ahalf);
        #pragma unroll
        for (int j = 0; j < 4; j++) av[j] = asrc[j];
        const float4* wsrc = (const float4*)(W + (size_t)(k0 + brow) * DMODEL + n0 + bcol);
        #pragma unroll
        for (int j = 0; j < 2; j++) wv[j] = wsrc[j];
        __syncthreads();

        #pragma unroll
        for (int j = 0; j < 4; j++) {
            float f[4] = {av[j].x, av[j].y, av[j].z, av[j].w};
            #pragma unroll
            for (int e = 0; e < 4; e += 2) {
                __nv_bfloat16 h0 = __float2bfloat16_rn(f[e]);
                __nv_bfloat16 h1 = __float2bfloat16_rn(f[e + 1]);
                __nv_bfloat16 l0 = __float2bfloat16_rn(f[e] - __bfloat162float(h0));
                __nv_bfloat16 l1 = __float2bfloat16_rn(f[e + 1] - __bfloat162float(h1));
                int off = arow * SKA + ahalf + j * 4 + e;
                *(__nv_bfloat162*)&Ah[off] = __nv_bfloat162(h0, h1);
                *(__nv_bfloat162*)&Al[off] = __nv_bfloat162(l0, l1);
            }
        }
        #pragma unroll
        for (int j = 0; j < 2; j++) {
            float f[4] = {wv[j].x, wv[j].y, wv[j].z, wv[j].w};
            #pragma unroll
            for (int e = 0; e < 4; e += 2) {
                __nv_bfloat16 h0 = __float2bfloat16_rn(f[e]);
                __nv_bfloat16 h1 = __float2bfloat16_rn(f[e + 1]);
                __nv_bfloat16 l0 = __float2bfloat16_rn(f[e] - __bfloat162float(h0));
                __nv_bfloat16 l1 = __float2bfloat16_rn(f[e + 1] - __bfloat162float(h1));
                int off = brow * SNB + bcol + j * 4 + e;
                *(__nv_bfloat162*)&Bh[off] = __nv_bfloat162(h0, h1);
                *(__nv_bfloat162*)&Bl[off] = __nv_bfloat162(l0, l1);
            }
        }
        __syncthreads();

        #pragma unroll
        for (int ks = 0; ks < 2; ks++) {
            const unsigned koffA = ks * 16 * 2;
            const unsigned koffB = (unsigned)(ks * 16 * SNB * 2);
            unsigned ah[2][4], al[2][4];
            #pragma unroll
            for (int mf = 0; mf < 2; mf++) {
                LDSM_X4(ah[mf][0], ah[mf][1], ah[mf][2], ah[mf][3], aAh[mf] + koffA);
                LDSM_X4(al[mf][0], al[mf][1], al[mf][2], al[mf][3], aAl[mf] + koffA);
            }
            unsigned bh[4][2], bl[4][2];
            #pragma unroll
            for (int nf2 = 0; nf2 < 2; nf2++) {
                unsigned r0, r1, r2, r3;
                LDSM_X4T(r0, r1, r2, r3, aBh[nf2] + koffB);
                bh[nf2 * 2][0] = r0;  bh[nf2 * 2][1] = r1;
                bh[nf2 * 2 + 1][0] = r2;  bh[nf2 * 2 + 1][1] = r3;
                LDSM_X4T(r0, r1, r2, r3, aBl[nf2] + koffB);
                bl[nf2 * 2][0] = r0;  bl[nf2 * 2][1] = r1;
                bl[nf2 * 2 + 1][0] = r2;  bl[nf2 * 2 + 1][1] = r3;
            }
            #pragma unroll
            for (int mf = 0; mf < 2; mf++)
                #pragma unroll
                for (int nf = 0; nf < 4; nf++) {
                    MMA_BF16(c[mf][nf], ah[mf], bh[nf]);
                    MMA_BF16(c[mf][nf], ah[mf], bl[nf]);
                    MMA_BF16(c[mf][nf], al[mf], bh[nf]);
                }
        }
    }

    #pragma unroll
    for (int mf = 0; mf < 2; mf++) {
        #pragma unroll
        for (int nf = 0; nf < 4; nf++) {
            int row = m0 + warp_m * 32 + mf * 16 + (lane >> 2);
            int col = n0 + warp_n * 32 + nf * 8 + (lane & 3) * 2;
            int h = col / DH, d = col % DH;
            float* base = Dst + (size_t)h * NTOK * DH;
            *(float2*)&base[(size_t)row * DH + d] =
                make_float2(c[mf][nf][0], c[mf][nf][1]);
            *(float2*)&base[(size_t)(row + 8) * DH + d] =
                make_float2(c[mf][nf][2], c[mf][nf][3]);
        }
    }
}

// ---------------------------------------------------------------------------
// Gather compacted fp32 K/V; zero-pad to multiple of KTILE (=32) rows.
// ---------------------------------------------------------------------------
__global__ __launch_bounds__(320) void gather_kernel() {
    const int sig = blockIdx.y + 1;
    const int head = blockIdx.z;
    const int kc = g_kcnt[sig];
    const int pad = (kc + KTILE - 1) & ~(KTILE - 1);
    const int jc = blockIdx.x * 32 + threadIdx.x / 10;
    const int c4 = threadIdx.x % 10;
    if (jc >= pad) return;

    size_t dst = ((size_t)((sig - 1) * HEADS + head) * NTOK + jc) * DH + c4 * 4;
    float4 kv = make_float4(0.f, 0.f, 0.f, 0.f);
    float4 vv = make_float4(0.f, 0.f, 0.f, 0.f);
    if (jc < kc) {
        int j = g_kidx[sig][jc];
        size_t src = ((size_t)head * NTOK + j) * DH + c4 * 4;
        kv = *(const float4*)(g_k + src);
        vv = *(const float4*)(g_v + src);
    }
    *(float4*)(g_kc + dst) = kv;
    *(float4*)(g_vc + dst) = vv;
}

// ---------------------------------------------------------------------------
// Per-head V column mean: two-stage (proven R11 version)
// ---------------------------------------------------------------------------
__global__ __launch_bounds__(320) void meanv1_kernel() {
    __shared__ float red[320];
    const int head = blockIdx.x;
    const int chunk = blockIdx.y;
    const int t = threadIdx.x;
    const int d = t % DH, r = t / DH;
    float s = 0.0f;
    const int j0 = chunk * 256;
    for (int j = j0 + r; j < j0 + 256; j += 8)
        s += g_v[((size_t)head * NTOK + j) * DH + d];
    red[t] = s;
    __syncthreads();
    if (r == 0) {
        float tot = 0.0f;
        #pragma unroll
        for (int rr = 0; rr < 8; rr++) tot += red[rr * DH + d];
        g_mvpart[chunk][head * DH + d] = tot;
    }
}

__global__ __launch_bounds__(320) void meanv2_kernel() {
    const int i = threadIdx.x;
    float s = 0.0f;
    #pragma unroll
    for (int c = 0; c < 16; c++) s += g_mvpart[c][i];
    g_meanv[i] = s * (1.0f / (float)NTOK);
}

// ---------------------------------------------------------------------------
// Flash attention, cp.async double-buffered (KTILE=32, same 20KB smem).
// 128 threads = 64 queries x 2 dim-halves; f32x2 math, log2 softmax.
// ---------------------------------------------------------------------------
__global__ __launch_bounds__(128) void attn_kernel() {
    if (blockIdx.x >= g_nunits) return;
    __shared__ __align__(16) float ksh[2][KTILE * DH];
    __shared__ __align__(16) float vsh[2][KTILE * DH];

    const int tid  = threadIdx.x;
    const int head = blockIdx.y;
    const int uix  = blockIdx.x;
    const int sig  = g_u_sig[uix];
    const int qoff = g_u_qoff[uix];
    const int qend = g_u_qend[uix];
    const int t_start = g_u_t0[uix];
    const int t_end   = g_u_t1[uix];
    const int spl  = g_u_spl[uix];
    const int q    = tid >> 1;
    const int half = tid & 1;
    const int ql   = qoff + q;
    const bool vq  = ql < qend;
    const int qi   = g_qidx[vq ? ql : qoff];
    const float scale = 0.15811388300841898f * 1.4426950408889634f;

    const float* Kb = g_kc + (size_t)((sig - 1) * HEADS + head) * NTOK * DH;
    const float* Vb = g_vc + (size_t)((sig - 1) * HEADS + head) * NTOK * DH;

    ull q2[10];
    {
        const float4* qp = (const float4*)(g_q + ((size_t)head * NTOK + qi) * DH + half * 20);
        #pragma unroll
        for (int i = 0; i < 5; i++) {
            float4 v = qp[i];
            PACK2(q2[2 * i + 0], v.x * scale, v.y * scale);
            PACK2(q2[2 * i + 1], v.z * scale, v.w * scale);
        }
    }

    float m = -FLT_MAX, l = 0.0f;
    ull acc2[10];
    #pragma unroll
    for (int d = 0; d < 10; d++) acc2[d] = 0ull;

    const int nt = (t_end - t_start + KTILE - 1) / KTILE;
    // 16B chunks per tile per array: 32*40*4/16 = 320
    // prologue: tile 0 -> buf 0
    {
        const char* kg = (const char*)(Kb + (size_t)t_start * DH);
        const char* vg = (const char*)(Vb + (size_t)t_start * DH);
        unsigned kd = s2u(&ksh[0][0]);
        unsigned vd = s2u(&vsh[0][0]);
        for (int c = tid; c < 320; c += 128) {
            CP_ASYNC16(kd + c * 16, kg + (size_t)c * 16);
            CP_ASYNC16(vd + c * 16, vg + (size_t)c * 16);
        }
        CP_COMMIT();
    }

    for (int it = 0; it < nt; it++) {
        const int t0 = t_start + it * KTILE;
        const int buf = it & 1;
        __syncthreads();   // prior compute done reading buf^1
        if (it + 1 < nt) {
            const char* kg = (const char*)(Kb + (size_t)(t0 + KTILE) * DH);
            const char* vg = (const char*)(Vb + (size_t)(t0 + KTILE) * DH);
            unsigned kd = s2u(&ksh[buf ^ 1][0]);
            unsigned vd = s2u(&vsh[buf ^ 1][0]);
            for (int c = tid; c < 320; c += 128) {
                CP_ASYNC16(kd + c * 16, kg + (size_t)c * 16);
                CP_ASYNC16(vd + c * 16, vg + (size_t)c * 16);
            }
            CP_COMMIT();
            CP_WAIT1();    // current tile's group complete; next stays in flight
        } else {
            CP_WAIT0();
        }
        __syncthreads();

        const float* kt = ksh[buf];
        const float* vt = vsh[buf];
        const int lim = (t_end - t0 < KTILE) ? (t_end - t0) : KTILE;
        for (int c = 0; c < lim; c += 16) {
            float s[16];
            #pragma unroll
            for (int j = 0; j < 16; j++) {
                const ulonglong2* kr =
                    (const ulonglong2*)(kt + (c + j) * DH + half * 20);
                ull sva = 0ull, svb = 0ull;
                ulonglong2 k0 = kr[0], k1 = kr[1], k2 = kr[2], k3 = kr[3], k4 = kr[4];
                FMA2(sva, q2[0], k0.x, sva);
                FMA2(svb, q2[1], k0.y, svb);
                FMA2(sva, q2[2], k1.x, sva);
                FMA2(svb, q2[3], k1.y, svb);
                FMA2(sva, q2[4], k2.x, sva);
                FMA2(svb, q2[5], k2.y, svb);
                FMA2(sva, q2[6], k3.x, sva);
                FMA2(svb, q2[7], k3.y, svb);
                FMA2(sva, q2[8], k4.x, sva);
                FMA2(svb, q2[9], k4.y, svb);
                float la, ha, lb, hb;
                UNPACK2(la, ha, sva);
                UNPACK2(lb, hb, svb);
                float svf = (la + ha) + (lb + hb);
                svf += __shfl_xor_sync(0xffffffffu, svf, 1);
                s[j] = (c + j < lim) ? svf : -FLT_MAX;
            }
            // tree max over 16
            float m01 = fmaxf(s[0], s[1]),   m23 = fmaxf(s[2], s[3]);
            float m45 = fmaxf(s[4], s[5]),   m67 = fmaxf(s[6], s[7]);
            float m89 = fmaxf(s[8], s[9]),   mab = fmaxf(s[10], s[11]);
            float mcd = fmaxf(s[12], s[13]), mef = fmaxf(s[14], s[15]);
            float m03 = fmaxf(m01, m23), m47 = fmaxf(m45, m67);
            float m8b = fmaxf(m89, mab), mcf = fmaxf(mcd, mef);
            float cmax = fmaxf(fmaxf(m03, m47), fmaxf(m8b, mcf));

            float mnew = fmaxf(m, cmax);
            float corr = ex2(m - mnew);
            l *= corr;
            {
                ull corr2;
                PACK2(corr2, corr, corr);
                #pragma unroll
                for (int d = 0; d < 10; d++) MUL2(acc2[d], acc2[d], corr2);
            }
            #pragma unroll
            for (int j = 0; j < 16; j++) {
                float pj = ex2(s[j] - mnew);
                l += pj;
                ull pj2;
                PACK2(pj2, pj, pj);
                const ulonglong2* vr =
                    (const ulonglong2*)(vt + (c + j) * DH + half * 20);
                ulonglong2 v0 = vr[0], v1 = vr[1], v2 = vr[2], v3 = vr[3], v4 = vr[4];
                FMA2(acc2[0], pj2, v0.x, acc2[0]);
                FMA2(acc2[1], pj2, v0.y, acc2[1]);
                FMA2(acc2[2], pj2, v1.x, acc2[2]);
                FMA2(acc2[3], pj2, v1.y, acc2[3]);
                FMA2(acc2[4], pj2, v2.x, acc2[4]);
                FMA2(acc2[5], pj2, v2.y, acc2[5]);
                FMA2(acc2[6], pj2, v3.x, acc2[6]);
                FMA2(acc2[7], pj2, v3.y, acc2[7]);
                FMA2(acc2[8], pj2, v4.x, acc2[8]);
                FMA2(acc2[9], pj2, v4.y, acc2[9]);
            }
            m = mnew;
        }
    }

    if (vq) {
        size_t base = (size_t)(spl * HEADS + head) * NTOK + ql;
        if (half == 0) {
            g_pm[base] = m;
            g_pl[base] = l;
        }
        float4* pp = (float4*)(g_pacc + base * DH + half * 20);
        #pragma unroll
        for (int d4 = 0; d4 < 5; d4++) {
            float4 r;
            UNPACK2(r.x, r.y, acc2[2 * d4 + 0]);
            UNPACK2(r.z, r.w, acc2[2 * d4 + 1]);
            pp[d4] = r;
        }
    }
}

// ---------------------------------------------------------------------------
// Merge split partials + meanV fill (fused; proven R10 version)
// ---------------------------------------------------------------------------
__global__ __launch_bounds__(256) void reduce_kernel() {
    const int idx = blockIdx.x * 256 + threadIdx.x;
    if (idx >= NTOK * HEADS) return;
    const int ql = idx / HEADS;
    const int head = idx % HEADS;
    const int nq0 = g_grp_cnt[0];
    const int qi = g_qidx[ql];
    float* op = g_o + (size_t)qi * DMODEL + head * DH;

    if (ql < nq0) {
        const float4* mv = (const float4*)(g_meanv + head * DH);
        #pragma unroll
        for (int d4 = 0; d4 < 10; d4++) *(float4*)(op + d4 * 4) = mv[d4];
        return;
    }

    int sig = 1;
    #pragma unroll
    for (int s = 2; s < 8; s++)
        if (ql >= g_grp_off[s]) sig = s;
    const int ns = g_nsplit[sig];

    float m = -FLT_MAX;
    for (int s = 0; s < ns; s++) {
        float ms = g_pm[(size_t)(s * HEADS + head) * NTOK + ql];
        m = fmaxf(m, ms);
    }
    float l = 0.0f;
    for (int s = 0; s < ns; s++) {
        size_t base = (size_t)(s * HEADS + head) * NTOK + ql;
        l += g_pl[base] * ex2(g_pm[base] - m);
    }
    const float inv = 1.0f / l;

    float sum[DH];
    #pragma unroll
    for (int d = 0; d < DH; d++) sum[d] = 0.0f;
    for (int s = 0; s < ns; s++) {
        size_t base = (size_t)(s * HEADS + head) * NTOK + ql;
        float w = ex2(g_pm[base] - m);
        const float4* pa = (const float4*)(g_pacc + base * DH);
        #pragma unroll
        for (int d4 = 0; d4 < 10; d4++) {
            float4 a = pa[d4];
            sum[d4 * 4 + 0] += w * a.x;
            sum[d4 * 4 + 1] += w * a.y;
            sum[d4 * 4 + 2] += w * a.z;
            sum[d4 * 4 + 3] += w * a.w;
        }
    }
    #pragma unroll
    for (int d4 = 0; d4 < 10; d4++) {
        float4 r;
        r.x = sum[d4 * 4 + 0] * inv;
        r.y = sum[d4 * 4 + 1] * inv;
        r.z = sum[d4 * 4 + 2] * inv;
        r.w = sum[d4 * 4 + 3] * inv;
        *(float4*)(op + d4 * 4) = r;
    }
}

// ---------------------------------------------------------------------------
// Output projection via bf16 split MMA (proven R11 version).
// ---------------------------------------------------------------------------
__global__ __launch_bounds__(256) void out_gemm(
    const float* __restrict__ Wo, const float* __restrict__ bo,
    float* __restrict__ out)
{
    __shared__ __nv_bfloat16 Ah[128 * SKA], Al[128 * SKA];
    __shared__ __nv_bfloat16 Bh[32 * SNB],  Bl[32 * SNB];

    const int tid  = threadIdx.x;
    const int lane = tid & 31;
    const int wid  = tid >> 5;
    const int warp_m = wid >> 1;
    const int warp_n = wid & 1;
    const int m0 = blockIdx.y * 128;
    const int n0 = blockIdx.x * 64;
    const int quad = lane >> 3, rr = lane & 7;

    float c[2][4][4];
    #pragma unroll
    for (int mf = 0; mf < 2; mf++)
        #pragma unroll
        for (int nf = 0; nf < 4; nf++)
            #pragma unroll
            for (int r = 0; r < 4; r++) c[mf][nf][r] = 0.0f;

    const int arow = tid >> 1, ahalf = (tid & 1) * 16;
    const int brow = tid >> 3, bcol = (tid & 7) * 8;

    unsigned aAh[2], aAl[2];
    #pragma unroll
    for (int mf = 0; mf < 2; mf++) {
        int mrow = warp_m * 32 + mf * 16 + (quad & 1) * 8 + rr;
        int kcol = (quad >> 1) * 8;
        aAh[mf] = s2u(&Ah[mrow * SKA + kcol]);
        aAl[mf] = s2u(&Al[mrow * SKA + kcol]);
    }
    unsigned aBh[2], aBl[2];
    #pragma unroll
    for (int nf2 = 0; nf2 < 2; nf2++) {
        int krow = (quad & 1) * 8 + rr;
        int ncol = warp_n * 32 + nf2 * 16 + (quad >> 1) * 8;
        aBh[nf2] = s2u(&Bh[krow * SNB + ncol]);
        aBl[nf2] = s2u(&Bl[krow * SNB + ncol]);
    }

    for (int k0 = 0; k0 < DMODEL; k0 += 32) {
        float4 av[4], wv[2];
        const float4* asrc = (const float4*)(g_o + (size_t)(m0 + arow) * DMODEL + k0 + ahalf);
        #pragma unroll
        for (int j = 0; j < 4; j++) av[j] = asrc[j];
        const float4* wsrc = (const float4*)(Wo + (size_t)(k0 + brow) * DMODEL + n0 + bcol);
        #pragma unroll
        for (int j = 0; j < 2; j++) wv[j] = wsrc[j];
        __syncthreads();

        #pragma unroll
        for (int j = 0; j < 4; j++) {
            float f[4] = {av[j].x, av[j].y, av[j].z, av[j].w};
            #pragma unroll
            for (int e = 0; e < 4; e += 2) {
                __nv_bfloat16 h0 = __float2bfloat16_rn(f[e]);
                __nv_bfloat16 h1 = __float2bfloat16_rn(f[e + 1]);
                __nv_bfloat16 l0 = __float2bfloat16_rn(f[e] - __bfloat162float(h0));
                __nv_bfloat16 l1 = __float2bfloat16_rn(f[e + 1] - __bfloat162float(h1));
                int off = arow * SKA + ahalf + j * 4 + e;
                *(__nv_bfloat162*)&Ah[off] = __nv_bfloat162(h0, h1);
                *(__nv_bfloat162*)&Al[off] = __nv_bfloat162(l0, l1);
            }
        }
        #pragma unroll
        for (int j = 0; j < 2; j++) {
            float f[4] = {wv[j].x, wv[j].y, wv[j].z, wv[j].w};
            #pragma unroll
            for (int e = 0; e < 4; e += 2) {
                __nv_bfloat16 h0 = __float2bfloat16_rn(f[e]);
                __nv_bfloat16 h1 = __float2bfloat16_rn(f[e + 1]);
                __nv_bfloat16 l0 = __float2bfloat16_rn(f[e] - __bfloat162float(h0));
                __nv_bfloat16 l1 = __float2bfloat16_rn(f[e + 1] - __bfloat162float(h1));
                int off = brow * SNB + bcol + j * 4 + e;
                *(__nv_bfloat162*)&Bh[off] = __nv_bfloat162(h0, h1);
                *(__nv_bfloat162*)&Bl[off] = __nv_bfloat162(l0, l1);
            }
        }
        __syncthreads();

        #pragma unroll
        for (int ks = 0; ks < 2; ks++) {
            const unsigned koffA = ks * 16 * 2;
            const unsigned koffB = (unsigned)(ks * 16 * SNB * 2);
            unsigned ah[2][4], al[2][4];
            #pragma unroll
            for (int mf = 0; mf < 2; mf++) {
                LDSM_X4(ah[mf][0], ah[mf][1], ah[mf][2], ah[mf][3], aAh[mf] + koffA);
                LDSM_X4(al[mf][0], al[mf][1], al[mf][2], al[mf][3], aAl[mf] + koffA);
            }
            unsigned bh[4][2], bl[4][2];
            #pragma unroll
            for (int nf2 = 0; nf2 < 2; nf2++) {
                unsigned r0, r1, r2, r3;
                LDSM_X4T(r0, r1, r2, r3, aBh[nf2] + koffB);
                bh[nf2 * 2][0] = r0;  bh[nf2 * 2][1] = r1;
                bh[nf2 * 2 + 1][0] = r2;  bh[nf2 * 2 + 1][1] = r3;
                LDSM_X4T(r0, r1, r2, r3, aBl[nf2] + koffB);
                bl[nf2 * 2][0] = r0;  bl[nf2 * 2][1] = r1;
                bl[nf2 * 2 + 1][0] = r2;  bl[nf2 * 2 + 1][1] = r3;
            }
            #pragma unroll
            for (int mf = 0; mf < 2; mf++)
                #pragma unroll
                for (int nf = 0; nf < 4; nf++) {
                    MMA_BF16(c[mf][nf], ah[mf], bh[nf]);
                    MMA_BF16(c[mf][nf], ah[mf], bl[nf]);
                    MMA_BF16(c[mf][nf], al[mf], bh[nf]);
                }
        }
    }

    #pragma unroll
    for (int mf = 0; mf < 2; mf++) {
        #pragma unroll
        for (int nf = 0; nf < 4; nf++) {
            int row = m0 + warp_m * 32 + mf * 16 + (lane >> 2);
            int col = n0 + warp_n * 32 + nf * 8 + (lane & 3) * 2;
            float2 b = *(const float2*)(bo + col);
            *(float2*)&out[(size_t)row * DMODEL + col] =
                make_float2(c[mf][nf][0] + b.x, c[mf][nf][1] + b.y);
            *(float2*)&out[(size_t)(row + 8) * DMODEL + col] =
                make_float2(c[mf][nf][2] + b.x, c[mf][nf][3] + b.y);
        }
    }
}

// ---------------------------------------------------------------------------
extern "C" void kernel_launch(void* const* d_in, const int* in_sizes, int n_in,
                              void* d_out, int out_size)
{
    const float* x  = (const float*)d_in[0];
    const float* gm = (const float*)d_in[1];
    const float* Wq = (const float*)d_in[2];
    const float* Wk = (const float*)d_in[3];
    const float* Wv = (const float*)d_in[4];
    const float* Wo = (const float*)d_in[5];
    const float* bo = (const float*)d_in[6];
    float* out = (float*)d_out;

    mask_kernel<<<2, 192>>>(gm);
    plan_kernel<<<1, 256>>>();

    dim3 gq(DMODEL / 64, NTOK / 128, 3);
    qkv_gemm<<<gq, 256>>>(x, Wq, Wk, Wv);

    dim3 gg(128, 7, HEADS);
    gather_kernel<<<gg, 320>>>();

    dim3 gm1(HEADS, 16);
    meanv1_kernel<<<gm1, 320>>>();
    meanv2_kernel<<<1, 320>>>();

    dim3 ga(MAXU, HEADS);
    attn_kernel<<<ga, 128>>>();

    reduce_kernel<<<(NTOK * HEADS + 255) / 256, 256>>>();

    dim3 go(DMODEL / 64, NTOK / 128);
    out_gemm<<<go, 256>>>(Wo, bo, out);
}

// round 14
// speedup vs baseline: 1.0396x; 1.0396x over previous
#include <cuda_runtime.h>
#include <cuda_bf16.h>
#include <float.h>

#define NTOK   4096
#define DMODEL 320
#define HEADS  8
#define DH     40
#define NPHASE 3
#define KTILE  64
#define QBLK   64
#define UT     4
#define MAXU   1152
#define MAXSPL 16

typedef unsigned long long ull;

#define FMA2(d, a, b, c) \
    asm("fma.rn.f32x2 %0, %1, %2, %3;" : "=l"(d) : "l"(a), "l"(b), "l"(c))
#define MUL2(d, a, b) \
    asm("mul.rn.f32x2 %0, %1, %2;" : "=l"(d) : "l"(a), "l"(b))
#define PACK2(d, lo, hi) \
    asm("mov.b64 %0, {%1, %2};" : "=l"(d) : "f"(lo), "f"(hi))
#define UNPACK2(lo, hi, v) \
    asm("mov.b64 {%0, %1}, %2;" : "=f"(lo), "=f"(hi) : "l"(v))

#define LDSM_X4(r0, r1, r2, r3, addr) \
    asm volatile("ldmatrix.sync.aligned.m8n8.x4.shared.b16 {%0,%1,%2,%3}, [%4];" \
        : "=r"(r0), "=r"(r1), "=r"(r2), "=r"(r3) : "r"(addr))
#define LDSM_X4T(r0, r1, r2, r3, addr) \
    asm volatile("ldmatrix.sync.aligned.m8n8.x4.trans.shared.b16 {%0,%1,%2,%3}, [%4];" \
        : "=r"(r0), "=r"(r1), "=r"(r2), "=r"(r3) : "r"(addr))
#define MMA_BF16(c, a, b) \
    asm volatile("mma.sync.aligned.m16n8k16.row.col.f32.bf16.bf16.f32 " \
        "{%0,%1,%2,%3}, {%4,%5,%6,%7}, {%8,%9}, {%0,%1,%2,%3};" \
        : "+f"((c)[0]), "+f"((c)[1]), "+f"((c)[2]), "+f"((c)[3]) \
        : "r"((a)[0]), "r"((a)[1]), "r"((a)[2]), "r"((a)[3]), \
          "r"((b)[0]), "r"((b)[1]))

// ---------------- scratch (__device__ globals; no allocation allowed) -------
__device__ float g_q[HEADS * NTOK * DH];
__device__ float g_k[HEADS * NTOK * DH];
__device__ float g_v[HEADS * NTOK * DH];
__device__ float g_o[NTOK * DMODEL];

// planning data
__device__ int g_grp_cnt[8], g_grp_off[8];
__device__ int g_qidx[NTOK];
__device__ int g_kcnt[8];
__device__ int g_kidx[8][NTOK];
__device__ int g_nsplit[8];
__device__ int g_u_sig[MAXU], g_u_qoff[MAXU], g_u_qend[MAXU];
__device__ int g_u_t0[MAXU], g_u_t1[MAXU], g_u_spl[MAXU];
__device__ int g_nunits;

__device__ float g_meanv[HEADS * DH];
__device__ float g_mvpart[16][HEADS * DH];

// split partials: indexed [spl][head][ql]
__device__ float g_pacc[MAXSPL * HEADS * NTOK * DH];
__device__ float g_pm[MAXSPL * HEADS * NTOK];
__device__ float g_pl[MAXSPL * HEADS * NTOK];

__device__ __forceinline__ float ex2(float x) {
    float r;
    asm("ex2.approx.ftz.f32 %0, %1;" : "=f"(r) : "f"(x));
    return r;
}
__device__ __forceinline__ unsigned s2u(const void* p) {
    return (unsigned)__cvta_generic_to_shared(p);
}

// ---------------------------------------------------------------------------
// Plan kernel (mask packing fused; proven R10/R12 version)
// ---------------------------------------------------------------------------
__global__ __launch_bounds__(256) void plan_kernel(const float* __restrict__ gm) {
    __shared__ unsigned smb[NPHASE * (NTOK / 32)];
    __shared__ int sq[8][256];
    __shared__ int sk[8][256];
    __shared__ int base_q[8];
    const int t = threadIdx.x;

    {
        unsigned bits = 0;
        #pragma unroll 8
        for (int b = 0; b < 32; b++)
            if (gm[t * 32 + b] != 0.0f) bits |= (1u << b);
        smb[t] = bits;
        if (t < 128) {
            unsigned bits2 = 0;
            #pragma unroll 8
            for (int b = 0; b < 32; b++)
                if (gm[(256 + t) * 32 + b] != 0.0f) bits2 |= (1u << b);
            smb[256 + t] = bits2;
        }
    }
    __syncthreads();

    unsigned bits_arr[16];
    int cq[8], ck[8];
    #pragma unroll
    for (int s = 0; s < 8; s++) { cq[s] = 0; ck[s] = 0; }

    for (int u = 0; u < 16; u++) {
        int i = t * 16 + u;
        unsigned b = 0;
        #pragma unroll
        for (int p = 0; p < NPHASE; p++)
            b |= ((smb[p * 128 + (i >> 5)] >> (i & 31)) & 1u) << p;
        bits_arr[u] = b;
        cq[b]++;
        #pragma unroll
        for (int s = 1; s < 8; s++)
            if (b & (unsigned)s) ck[s]++;
    }
    #pragma unroll
    for (int s = 0; s < 8; s++) { sq[s][t] = cq[s]; sk[s][t] = ck[s]; }
    __syncthreads();

    for (int g = 0; g < 15; g++) {
        int* arr = (g < 8) ? sq[g] : sk[g - 7];
        for (int off = 1; off < 256; off <<= 1) {
            int u = (t >= off) ? arr[t - off] : 0;
            __syncthreads();
            arr[t] += u;
            __syncthreads();
        }
    }

    if (t == 0) {
        int acc = 0;
        for (int s = 0; s < 8; s++) {
            base_q[s] = acc;
            g_grp_off[s] = acc;
            int tot = sq[s][255];
            g_grp_cnt[s] = tot;
            acc += tot;
        }
        int nu = 0;
        for (int s = 1; s < 8; s++) {
            int kc = sk[s][255];
            g_kcnt[s] = kc;
            int cnt = sq[s][255], off = base_q[s];
            int tiles = (kc + KTILE - 1) / KTILE;
            int ns = (tiles + UT - 1) / UT;
            g_nsplit[s] = ns;
            for (int b = 0; b * QBLK < cnt; b++) {
                for (int sp = 0; sp < ns; sp++) {
                    g_u_sig[nu] = s;
                    g_u_qoff[nu] = off + b * QBLK;
                    g_u_qend[nu] = off + cnt;
                    g_u_t0[nu] = sp * UT * KTILE;
                    int t1 = (sp + 1) * UT * KTILE;
                    g_u_t1[nu] = (t1 < kc) ? t1 : kc;
                    g_u_spl[nu] = sp;
                    nu++;
                }
            }
        }
        g_nunits = nu;
    }
    __syncthreads();

    int qcur[8], kcur[8];
    #pragma unroll
    for (int s = 0; s < 8; s++) {
        qcur[s] = base_q[s] + sq[s][t] - cq[s];
        kcur[s] = sk[s][t] - ck[s];
    }
    for (int u = 0; u < 16; u++) {
        int i = t * 16 + u;
        unsigned b = bits_arr[u];
        g_qidx[qcur[b]++] = i;
        #pragma unroll
        for (int s = 1; s < 8; s++)
            if (b & (unsigned)s) g_kidx[s][kcur[s]++] = i;
    }
}

// ---------------------------------------------------------------------------
// QKV projection via bf16 split-precision MMA (proven R10 version).
// ---------------------------------------------------------------------------
#define SKA 40
#define SNB 72

__global__ __launch_bounds__(256) void qkv_gemm(
    const float* __restrict__ X,
    const float* __restrict__ Wq, const float* __restrict__ Wk,
    const float* __restrict__ Wv)
{
    const float* W = (blockIdx.z == 0) ? Wq : (blockIdx.z == 1) ? Wk : Wv;
    float* Dst = (blockIdx.z == 0) ? g_q : (blockIdx.z == 1) ? g_k : g_v;

    __shared__ __nv_bfloat16 Ah[128 * SKA], Al[128 * SKA];
    __shared__ __nv_bfloat16 Bh[32 * SNB],  Bl[32 * SNB];

    const int tid  = threadIdx.x;
    const int lane = tid & 31;
    const int wid  = tid >> 5;
    const int warp_m = wid >> 1;
    const int warp_n = wid & 1;
    const int m0 = blockIdx.y * 128;
    const int n0 = blockIdx.x * 64;
    const int quad = lane >> 3, rr = lane & 7;

    float c[2][4][4];
    #pragma unroll
    for (int mf = 0; mf < 2; mf++)
        #pragma unroll
        for (int nf = 0; nf < 4; nf++)
            #pragma unroll
            for (int r = 0; r < 4; r++) c[mf][nf][r] = 0.0f;

    const int arow = tid >> 1, ahalf = (tid & 1) * 16;
    const int brow = tid >> 3, bcol = (tid & 7) * 8;

    unsigned aAh[2], aAl[2];
    #pragma unroll
    for (int mf = 0; mf < 2; mf++) {
        int mrow = warp_m * 32 + mf * 16 + (quad & 1) * 8 + rr;
        int kcol = (quad >> 1) * 8;
        aAh[mf] = s2u(&Ah[mrow * SKA + kcol]);
        aAl[mf] = s2u(&Al[mrow * SKA + kcol]);
    }
    unsigned aBh[2], aBl[2];
    #pragma unroll
    for (int nf2 = 0; nf2 < 2; nf2++) {
        int krow = (quad & 1) * 8 + rr;
        int ncol = warp_n * 32 + nf2 * 16 + (quad >> 1) * 8;
        aBh[nf2] = s2u(&Bh[krow * SNB + ncol]);
        aBl[nf2] = s2u(&Bl[krow * SNB + ncol]);
    }

    for (int k0 = 0; k0 < DMODEL; k0 += 32) {
        float4 av[4], wv[2];
        const float4* asrc = (const float4*)(X + (size_t)(m0 + arow) * DMODEL + k0 + ahalf);
        #pragma unroll
        for (int j = 0; j < 4; j++) av[j] = asrc[j];
        const float4* wsrc = (const float4*)(W + (size_t)(k0 + brow) * DMODEL + n0 + bcol);
        #pragma unroll
        for (int j = 0; j < 2; j++) wv[j] = wsrc[j];
        __syncthreads();

        #pragma unroll
        for (int j = 0; j < 4; j++) {
            float f[4] = {av[j].x, av[j].y, av[j].z, av[j].w};
            #pragma unroll
            for (int e = 0; e < 4; e += 2) {
                __nv_bfloat16 h0 = __float2bfloat16_rn(f[e]);
                __nv_bfloat16 h1 = __float2bfloat16_rn(f[e + 1]);
                __nv_bfloat16 l0 = __float2bfloat16_rn(f[e] - __bfloat162float(h0));
                __nv_bfloat16 l1 = __float2bfloat16_rn(f[e + 1] - __bfloat162float(h1));
                int off = arow * SKA + ahalf + j * 4 + e;
                *(__nv_bfloat162*)&Ah[off] = __nv_bfloat162(h0, h1);
                *(__nv_bfloat162*)&Al[off] = __nv_bfloat162(l0, l1);
            }
        }
        #pragma unroll
        for (int j = 0; j < 2; j++) {
            float f[4] = {wv[j].x, wv[j].y, wv[j].z, wv[j].w};
            #pragma unroll
            for (int e = 0; e < 4; e += 2) {
                __nv_bfloat16 h0 = __float2bfloat16_rn(f[e]);
                __nv_bfloat16 h1 = __float2bfloat16_rn(f[e + 1]);
                __nv_bfloat16 l0 = __float2bfloat16_rn(f[e] - __bfloat162float(h0));
                __nv_bfloat16 l1 = __float2bfloat16_rn(f[e + 1] - __bfloat162float(h1));
                int off = brow * SNB + bcol + j * 4 + e;
                *(__nv_bfloat162*)&Bh[off] = __nv_bfloat162(h0, h1);
                *(__nv_bfloat162*)&Bl[off] = __nv_bfloat162(l0, l1);
            }
        }
        __syncthreads();

        #pragma unroll
        for (int ks = 0; ks < 2; ks++) {
            const unsigned koffA = ks * 16 * 2;
            const unsigned koffB = (unsigned)(ks * 16 * SNB * 2);
            unsigned ah[2][4], al[2][4];
            #pragma unroll
            for (int mf = 0; mf < 2; mf++) {
                LDSM_X4(ah[mf][0], ah[mf][1], ah[mf][2], ah[mf][3], aAh[mf] + koffA);
                LDSM_X4(al[mf][0], al[mf][1], al[mf][2], al[mf][3], aAl[mf] + koffA);
            }
            unsigned bh[4][2], bl[4][2];
            #pragma unroll
            for (int nf2 = 0; nf2 < 2; nf2++) {
                unsigned r0, r1, r2, r3;
                LDSM_X4T(r0, r1, r2, r3, aBh[nf2] + koffB);
                bh[nf2 * 2][0] = r0;  bh[nf2 * 2][1] = r1;
                bh[nf2 * 2 + 1][0] = r2;  bh[nf2 * 2 + 1][1] = r3;
                LDSM_X4T(r0, r1, r2, r3, aBl[nf2] + koffB);
                bl[nf2 * 2][0] = r0;  bl[nf2 * 2][1] = r1;
                bl[nf2 * 2 + 1][0] = r2;  bl[nf2 * 2 + 1][1] = r3;
            }
            #pragma unroll
            for (int mf = 0; mf < 2; mf++)
                #pragma unroll
                for (int nf = 0; nf < 4; nf++) {
                    MMA_BF16(c[mf][nf], ah[mf], bh[nf]);
                    MMA_BF16(c[mf][nf], ah[mf], bl[nf]);
                    MMA_BF16(c[mf][nf], al[mf], bh[nf]);
                }
        }
    }

    #pragma unroll
    for (int mf = 0; mf < 2; mf++) {
        #pragma unroll
        for (int nf = 0; nf < 4; nf++) {
            int row = m0 + warp_m * 32 + mf * 16 + (lane >> 2);
            int col = n0 + warp_n * 32 + nf * 8 + (lane & 3) * 2;
            int h = col / DH, d = col % DH;
            float* base = Dst + (size_t)h * NTOK * DH;
            *(float2*)&base[(size_t)row * DH + d] =
                make_float2(c[mf][nf][0], c[mf][nf][1]);
            *(float2*)&base[(size_t)(row + 8) * DH + d] =
                make_float2(c[mf][nf][2], c[mf][nf][3]);
        }
    }
}

// ---------------------------------------------------------------------------
// Per-head V column mean: two-stage (proven R11 version)
// ---------------------------------------------------------------------------
__global__ __launch_bounds__(320) void meanv1_kernel() {
    __shared__ float red[320];
    const int head = blockIdx.x;
    const int chunk = blockIdx.y;
    const int t = threadIdx.x;
    const int d = t % DH, r = t / DH;
    float s = 0.0f;
    const int j0 = chunk * 256;
    for (int j = j0 + r; j < j0 + 256; j += 8)
        s += g_v[((size_t)head * NTOK + j) * DH + d];
    red[t] = s;
    __syncthreads();
    if (r == 0) {
        float tot = 0.0f;
        #pragma unroll
        for (int rr = 0; rr < 8; rr++) tot += red[rr * DH + d];
        g_mvpart[chunk][head * DH + d] = tot;
    }
}

__global__ __launch_bounds__(320) void meanv2_kernel() {
    const int i = threadIdx.x;
    float s = 0.0f;
    #pragma unroll
    for (int c = 0; c < 16; c++) s += g_mvpart[c][i];
    g_meanv[i] = s * (1.0f / (float)NTOK);
}

// ---------------------------------------------------------------------------
// Flash attention over uniform work units (R12 loop body), reading K/V
// DIRECTLY from g_k/g_v via g_kidx indirection (gather kernel eliminated;
// g_k/g_v are 5.2MB total -> L2-resident). Pad rows clamp to index 0 and
// are neutralized by the existing -FLT_MAX score masking (pj == 0).
// 128 threads = 64 queries x 2 dim-halves; f32x2 math, log2 softmax.
// ---------------------------------------------------------------------------
__global__ __launch_bounds__(128) void attn_kernel() {
    if (blockIdx.x >= g_nunits) return;
    __shared__ __align__(16) float ksh[KTILE * DH];
    __shared__ __align__(16) float vsh[KTILE * DH];

    const int tid  = threadIdx.x;
    const int head = blockIdx.y;
    const int uix  = blockIdx.x;
    const int sig  = g_u_sig[uix];
    const int qoff = g_u_qoff[uix];
    const int qend = g_u_qend[uix];
    const int t_start = g_u_t0[uix];
    const int t_end   = g_u_t1[uix];
    const int spl  = g_u_spl[uix];
    const int q    = tid >> 1;
    const int half = tid & 1;
    const int ql   = qoff + q;
    const bool vq  = ql < qend;
    const int qi   = g_qidx[vq ? ql : qoff];
    const float scale = 0.15811388300841898f * 1.4426950408889634f;

    const float* Kh = g_k + (size_t)head * NTOK * DH;
    const float* Vh = g_v + (size_t)head * NTOK * DH;
    const int* kidx = g_kidx[sig];

    ull q2[10];
    {
        const float4* qp = (const float4*)(g_q + ((size_t)head * NTOK + qi) * DH + half * 20);
        #pragma unroll
        for (int i = 0; i < 5; i++) {
            float4 v = qp[i];
            PACK2(q2[2 * i + 0], v.x * scale, v.y * scale);
            PACK2(q2[2 * i + 1], v.z * scale, v.w * scale);
        }
    }

    float m = -FLT_MAX, l = 0.0f;
    ull acc2[10];
    #pragma unroll
    for (int d = 0; d < 10; d++) acc2[d] = 0ull;

    for (int t0 = t_start; t0 < t_end; t0 += KTILE) {
        __syncthreads();
        // indirect tile load: each float4 i covers (row = i/10, c4 = i%10);
        // rows beyond t_end clamp to key 0 (masked later)
        float4* ks4 = (float4*)ksh;
        float4* vs4 = (float4*)vsh;
        #pragma unroll
        for (int i = tid; i < KTILE * 10; i += 128) {
            int row = i / 10, c4 = i % 10;
            int gr = t0 + row;
            int idx = (gr < t_end) ? kidx[gr] : 0;
            size_t src = (size_t)idx * DH + c4 * 4;
            ks4[i] = *(const float4*)(Kh + src);
            vs4[i] = *(const float4*)(Vh + src);
        }
        __syncthreads();

        const int lim = (t_end - t0 < KTILE) ? (t_end - t0) : KTILE;
        for (int c = 0; c < lim; c += 16) {
            float s[16];
            float cmax = -FLT_MAX;
            #pragma unroll
            for (int j = 0; j < 16; j++) {
                const ulonglong2* kr =
                    (const ulonglong2*)(ksh + (c + j) * DH + half * 20);
                ull sva = 0ull, svb = 0ull;
                ulonglong2 k0 = kr[0], k1 = kr[1], k2 = kr[2], k3 = kr[3], k4 = kr[4];
                FMA2(sva, q2[0], k0.x, sva);
                FMA2(svb, q2[1], k0.y, svb);
                FMA2(sva, q2[2], k1.x, sva);
                FMA2(svb, q2[3], k1.y, svb);
                FMA2(sva, q2[4], k2.x, sva);
                FMA2(svb, q2[5], k2.y, svb);
                FMA2(sva, q2[6], k3.x, sva);
                FMA2(svb, q2[7], k3.y, svb);
                FMA2(sva, q2[8], k4.x, sva);
                FMA2(svb, q2[9], k4.y, svb);
                float la, ha, lb, hb;
                UNPACK2(la, ha, sva);
                UNPACK2(lb, hb, svb);
                float svf = (la + ha) + (lb + hb);
                svf += __shfl_xor_sync(0xffffffffu, svf, 1);
                s[j] = (c + j < lim) ? svf : -FLT_MAX;
                cmax = fmaxf(cmax, s[j]);
            }
            float mnew = fmaxf(m, cmax);
            float corr = ex2(m - mnew);
            l *= corr;
            {
                ull corr2;
                PACK2(corr2, corr, corr);
                #pragma unroll
                for (int d = 0; d < 10; d++) MUL2(acc2[d], acc2[d], corr2);
            }
            #pragma unroll
            for (int j = 0; j < 16; j++) {
                float pj = ex2(s[j] - mnew);
                l += pj;
                ull pj2;
                PACK2(pj2, pj, pj);
                const ulonglong2* vr =
                    (const ulonglong2*)(vsh + (c + j) * DH + half * 20);
                ulonglong2 v0 = vr[0], v1 = vr[1], v2 = vr[2], v3 = vr[3], v4 = vr[4];
                FMA2(acc2[0], pj2, v0.x, acc2[0]);
                FMA2(acc2[1], pj2, v0.y, acc2[1]);
                FMA2(acc2[2], pj2, v1.x, acc2[2]);
                FMA2(acc2[3], pj2, v1.y, acc2[3]);
                FMA2(acc2[4], pj2, v2.x, acc2[4]);
                FMA2(acc2[5], pj2, v2.y, acc2[5]);
                FMA2(acc2[6], pj2, v3.x, acc2[6]);
                FMA2(acc2[7], pj2, v3.y, acc2[7]);
                FMA2(acc2[8], pj2, v4.x, acc2[8]);
                FMA2(acc2[9], pj2, v4.y, acc2[9]);
            }
            m = mnew;
        }
    }

    if (vq) {
        size_t base = (size_t)(spl * HEADS + head) * NTOK + ql;
        if (half == 0) {
            g_pm[base] = m;
            g_pl[base] = l;
        }
        float4* pp = (float4*)(g_pacc + base * DH + half * 20);
        #pragma unroll
        for (int d4 = 0; d4 < 5; d4++) {
            float4 r;
            UNPACK2(r.x, r.y, acc2[2 * d4 + 0]);
            UNPACK2(r.z, r.w, acc2[2 * d4 + 1]);
            pp[d4] = r;
        }
    }
}

// ---------------------------------------------------------------------------
// Merge split partials + meanV fill (fused; proven R10 version)
// ---------------------------------------------------------------------------
__global__ __launch_bounds__(256) void reduce_kernel() {
    const int idx = blockIdx.x * 256 + threadIdx.x;
    if (idx >= NTOK * HEADS) return;
    const int ql = idx / HEADS;
    const int head = idx % HEADS;
    const int nq0 = g_grp_cnt[0];
    const int qi = g_qidx[ql];
    float* op = g_o + (size_t)qi * DMODEL + head * DH;

    if (ql < nq0) {
        const float4* mv = (const float4*)(g_meanv + head * DH);
        #pragma unroll
        for (int d4 = 0; d4 < 10; d4++) *(float4*)(op + d4 * 4) = mv[d4];
        return;
    }

    int sig = 1;
    #pragma unroll
    for (int s = 2; s < 8; s++)
        if (ql >= g_grp_off[s]) sig = s;
    const int ns = g_nsplit[sig];

    float m = -FLT_MAX;
    for (int s = 0; s < ns; s++) {
        float ms = g_pm[(size_t)(s * HEADS + head) * NTOK + ql];
        m = fmaxf(m, ms);
    }
    float l = 0.0f;
    for (int s = 0; s < ns; s++) {
        size_t base = (size_t)(s * HEADS + head) * NTOK + ql;
        l += g_pl[base] * ex2(g_pm[base] - m);
    }
    const float inv = 1.0f / l;

    float sum[DH];
    #pragma unroll
    for (int d = 0; d < DH; d++) sum[d] = 0.0f;
    for (int s = 0; s < ns; s++) {
        size_t base = (size_t)(s * HEADS + head) * NTOK + ql;
        float w = ex2(g_pm[base] - m);
        const float4* pa = (const float4*)(g_pacc + base * DH);
        #pragma unroll
        for (int d4 = 0; d4 < 10; d4++) {
            float4 a = pa[d4];
            sum[d4 * 4 + 0] += w * a.x;
            sum[d4 * 4 + 1] += w * a.y;
            sum[d4 * 4 + 2] += w * a.z;
            sum[d4 * 4 + 3] += w * a.w;
        }
    }
    #pragma unroll
    for (int d4 = 0; d4 < 10; d4++) {
        float4 r;
        r.x = sum[d4 * 4 + 0] * inv;
        r.y = sum[d4 * 4 + 1] * inv;
        r.z = sum[d4 * 4 + 2] * inv;
        r.w = sum[d4 * 4 + 3] * inv;
        *(float4*)(op + d4 * 4) = r;
    }
}

// ---------------------------------------------------------------------------
// Output projection via bf16 split MMA (proven R11 version).
// ---------------------------------------------------------------------------
__global__ __launch_bounds__(256) void out_gemm(
    const float* __restrict__ Wo, const float* __restrict__ bo,
    float* __restrict__ out)
{
    __shared__ __nv_bfloat16 Ah[128 * SKA], Al[128 * SKA];
    __shared__ __nv_bfloat16 Bh[32 * SNB],  Bl[32 * SNB];

    const int tid  = threadIdx.x;
    const int lane = tid & 31;
    const int wid  = tid >> 5;
    const int warp_m = wid >> 1;
    const int warp_n = wid & 1;
    const int m0 = blockIdx.y * 128;
    const int n0 = blockIdx.x * 64;
    const int quad = lane >> 3, rr = lane & 7;

    float c[2][4][4];
    #pragma unroll
    for (int mf = 0; mf < 2; mf++)
        #pragma unroll
        for (int nf = 0; nf < 4; nf++)
            #pragma unroll
            for (int r = 0; r < 4; r++) c[mf][nf][r] = 0.0f;

    const int arow = tid >> 1, ahalf = (tid & 1) * 16;
    const int brow = tid >> 3, bcol = (tid & 7) * 8;

    unsigned aAh[2], aAl[2];
    #pragma unroll
    for (int mf = 0; mf < 2; mf++) {
        int mrow = warp_m * 32 + mf * 16 + (quad & 1) * 8 + rr;
        int kcol = (quad >> 1) * 8;
        aAh[mf] = s2u(&Ah[mrow * SKA + kcol]);
        aAl[mf] = s2u(&Al[mrow * SKA + kcol]);
    }
    unsigned aBh[2], aBl[2];
    #pragma unroll
    for (int nf2 = 0; nf2 < 2; nf2++) {
        int krow = (quad & 1) * 8 + rr;
        int ncol = warp_n * 32 + nf2 * 16 + (quad >> 1) * 8;
        aBh[nf2] = s2u(&Bh[krow * SNB + ncol]);
        aBl[nf2] = s2u(&Bl[krow * SNB + ncol]);
    }

    for (int k0 = 0; k0 < DMODEL; k0 += 32) {
        float4 av[4], wv[2];
        const float4* asrc = (const float4*)(g_o + (size_t)(m0 + arow) * DMODEL + k0 + ahalf);
        #pragma unroll
        for (int j = 0; j < 4; j++) av[j] = asrc[j];
        const float4* wsrc = (const float4*)(Wo + (size_t)(k0 + brow) * DMODEL + n0 + bcol);
        #pragma unroll
        for (int j = 0; j < 2; j++) wv[j] = wsrc[j];
        __syncthreads();

        #pragma unroll
        for (int j = 0; j < 4; j++) {
            float f[4] = {av[j].x, av[j].y, av[j].z, av[j].w};
            #pragma unroll
            for (int e = 0; e < 4; e += 2) {
                __nv_bfloat16 h0 = __float2bfloat16_rn(f[e]);
                __nv_bfloat16 h1 = __float2bfloat16_rn(f[e + 1]);
                __nv_bfloat16 l0 = __float2bfloat16_rn(f[e] - __bfloat162float(h0));
                __nv_bfloat16 l1 = __float2bfloat16_rn(f[e + 1] - __bfloat162float(h1));
                int off = arow * SKA + ahalf + j * 4 + e;
                *(__nv_bfloat162*)&Ah[off] = __nv_bfloat162(h0, h1);
                *(__nv_bfloat162*)&Al[off] = __nv_bfloat162(l0, l1);
            }
        }
        #pragma unroll
        for (int j = 0; j < 2; j++) {
            float f[4] = {wv[j].x, wv[j].y, wv[j].z, wv[j].w};
            #pragma unroll
            for (int e = 0; e < 4; e += 2) {
                __nv_bfloat16 h0 = __float2bfloat16_rn(f[e]);
                __nv_bfloat16 h1 = __float2bfloat16_rn(f[e + 1]);
                __nv_bfloat16 l0 = __float2bfloat16_rn(f[e] - __bfloat162float(h0));
                __nv_bfloat16 l1 = __float2bfloat16_rn(f[e + 1] - __bfloat162float(h1));
                int off = brow * SNB + bcol + j * 4 + e;
                *(__nv_bfloat162*)&Bh[off] = __nv_bfloat162(h0, h1);
                *(__nv_bfloat162*)&Bl[off] = __nv_bfloat162(l0, l1);
            }
        }
        __syncthreads();

        #pragma unroll
        for (int ks = 0; ks < 2; ks++) {
            const unsigned koffA = ks * 16 * 2;
            const unsigned koffB = (unsigned)(ks * 16 * SNB * 2);
            unsigned ah[2][4], al[2][4];
            #pragma unroll
            for (int mf = 0; mf < 2; mf++) {
                LDSM_X4(ah[mf][0], ah[mf][1], ah[mf][2], ah[mf][3], aAh[mf] + koffA);
                LDSM_X4(al[mf][0], al[mf][1], al[mf][2], al[mf][3], aAl[mf] + koffA);
            }
            unsigned bh[4][2], bl[4][2];
            #pragma unroll
            for (int nf2 = 0; nf2 < 2; nf2++) {
                unsigned r0, r1, r2, r3;
                LDSM_X4T(r0, r1, r2, r3, aBh[nf2] + koffB);
                bh[nf2 * 2][0] = r0;  bh[nf2 * 2][1] = r1;
                bh[nf2 * 2 + 1][0] = r2;  bh[nf2 * 2 + 1][1] = r3;
                LDSM_X4T(r0, r1, r2, r3, aBl[nf2] + koffB);
                bl[nf2 * 2][0] = r0;  bl[nf2 * 2][1] = r1;
                bl[nf2 * 2 + 1][0] = r2;  bl[nf2 * 2 + 1][1] = r3;
            }
            #pragma unroll
            for (int mf = 0; mf < 2; mf++)
                #pragma unroll
                for (int nf = 0; nf < 4; nf++) {
                    MMA_BF16(c[mf][nf], ah[mf], bh[nf]);
                    MMA_BF16(c[mf][nf], ah[mf], bl[nf]);
                    MMA_BF16(c[mf][nf], al[mf], bh[nf]);
                }
        }
    }

    #pragma unroll
    for (int mf = 0; mf < 2; mf++) {
        #pragma unroll
        for (int nf = 0; nf < 4; nf++) {
            int row = m0 + warp_m * 32 + mf * 16 + (lane >> 2);
            int col = n0 + warp_n * 32 + nf * 8 + (lane & 3) * 2;
            float2 b = *(const float2*)(bo + col);
            *(float2*)&out[(size_t)row * DMODEL + col] =
                make_float2(c[mf][nf][0] + b.x, c[mf][nf][1] + b.y);
            *(float2*)&out[(size_t)(row + 8) * DMODEL + col] =
                make_float2(c[mf][nf][2] + b.x, c[mf][nf][3] + b.y);
        }
    }
}

// ---------------------------------------------------------------------------
extern "C" void kernel_launch(void* const* d_in, const int* in_sizes, int n_in,
                              void* d_out, int out_size)
{
    const float* x  = (const float*)d_in[0];
    const float* gm = (const float*)d_in[1];
    const float* Wq = (const float*)d_in[2];
    const float* Wk = (const float*)d_in[3];
    const float* Wv = (const float*)d_in[4];
    const float* Wo = (const float*)d_in[5];
    const float* bo = (const float*)d_in[6];
    float* out = (float*)d_out;

    plan_kernel<<<1, 256>>>(gm);

    dim3 gq(DMODEL / 64, NTOK / 128, 3);
    qkv_gemm<<<gq, 256>>>(x, Wq, Wk, Wv);

    dim3 gm1(HEADS, 16);
    meanv1_kernel<<<gm1, 320>>>();
    meanv2_kernel<<<1, 320>>>();

    dim3 ga(MAXU, HEADS);
    attn_kernel<<<ga, 128>>>();

    reduce_kernel<<<(NTOK * HEADS + 255) / 256, 256>>>();

    dim3 go(DMODEL / 64, NTOK / 128);
    out_gemm<<<go, 256>>>(Wo, bo, out);
}

// round 16
// speedup vs baseline: 1.0716x; 1.0308x over previous
#include <cuda_runtime.h>
#include <cuda_bf16.h>
#include <float.h>

#define NTOK   4096
#define DMODEL 320
#define HEADS  8
#define DH     40
#define NPHASE 3
#define KTILE  64
#define QBLK   64
#define UT     4
#define MAXU   1152
#define MAXSPL 16

typedef unsigned long long ull;

#define FMA2(d, a, b, c) \
    asm("fma.rn.f32x2 %0, %1, %2, %3;" : "=l"(d) : "l"(a), "l"(b), "l"(c))
#define MUL2(d, a, b) \
    asm("mul.rn.f32x2 %0, %1, %2;" : "=l"(d) : "l"(a), "l"(b))
#define PACK2(d, lo, hi) \
    asm("mov.b64 %0, {%1, %2};" : "=l"(d) : "f"(lo), "f"(hi))
#define UNPACK2(lo, hi, v) \
    asm("mov.b64 {%0, %1}, %2;" : "=f"(lo), "=f"(hi) : "l"(v))

#define LDSM_X4(r0, r1, r2, r3, addr) \
    asm volatile("ldmatrix.sync.aligned.m8n8.x4.shared.b16 {%0,%1,%2,%3}, [%4];" \
        : "=r"(r0), "=r"(r1), "=r"(r2), "=r"(r3) : "r"(addr))
#define LDSM_X4T(r0, r1, r2, r3, addr) \
    asm volatile("ldmatrix.sync.aligned.m8n8.x4.trans.shared.b16 {%0,%1,%2,%3}, [%4];" \
        : "=r"(r0), "=r"(r1), "=r"(r2), "=r"(r3) : "r"(addr))
#define MMA_BF16(c, a, b) \
    asm volatile("mma.sync.aligned.m16n8k16.row.col.f32.bf16.bf16.f32 " \
        "{%0,%1,%2,%3}, {%4,%5,%6,%7}, {%8,%9}, {%0,%1,%2,%3};" \
        : "+f"((c)[0]), "+f"((c)[1]), "+f"((c)[2]), "+f"((c)[3]) \
        : "r"((a)[0]), "r"((a)[1]), "r"((a)[2]), "r"((a)[3]), \
          "r"((b)[0]), "r"((b)[1]))

// ---------------- scratch (__device__ globals; no allocation allowed) -------
__device__ float g_q[HEADS * NTOK * DH];
__device__ float g_k[HEADS * NTOK * DH];
__device__ float g_v[HEADS * NTOK * DH];
__device__ float g_o[NTOK * DMODEL];

// planning data
__device__ int g_grp_cnt[8], g_grp_off[8];
__device__ int g_qidx[NTOK];
__device__ int g_kcnt[8];
__device__ int g_kidx[8][NTOK];
__device__ int g_nsplit[8];
__device__ int g_u_sig[MAXU], g_u_qoff[MAXU], g_u_qend[MAXU];
__device__ int g_u_t0[MAXU], g_u_t1[MAXU], g_u_spl[MAXU];
__device__ int g_nunits;

__device__ float g_meanv[HEADS * DH];
__device__ float g_mvpart[16][HEADS * DH];

// split partials: indexed [spl][head][ql]
__device__ float g_pacc[MAXSPL * HEADS * NTOK * DH];
__device__ float g_pm[MAXSPL * HEADS * NTOK];
__device__ float g_pl[MAXSPL * HEADS * NTOK];

__device__ __forceinline__ float ex2(float x) {
    float r;
    asm("ex2.approx.ftz.f32 %0, %1;" : "=f"(r) : "f"(x));
    return r;
}
__device__ __forceinline__ unsigned s2u(const void* p) {
    return (unsigned)__cvta_generic_to_shared(p);
}

// ---------------------------------------------------------------------------
// Plan kernel: mask packing fused; all 15 scans done per-round (16 barriers
// total instead of 240); unit table built by ALL threads (deterministic
// closed-form mapping) instead of one serial thread.
// ---------------------------------------------------------------------------
__global__ __launch_bounds__(256) void plan_kernel(const float* __restrict__ gm) {
    __shared__ unsigned smb[NPHASE * (NTOK / 32)];
    __shared__ int sq[8][256];
    __shared__ int sk[8][256];
    const int t = threadIdx.x;

    {
        unsigned bits = 0;
        #pragma unroll 8
        for (int b = 0; b < 32; b++)
            if (gm[t * 32 + b] != 0.0f) bits |= (1u << b);
        smb[t] = bits;
        if (t < 128) {
            unsigned bits2 = 0;
            #pragma unroll 8
            for (int b = 0; b < 32; b++)
                if (gm[(256 + t) * 32 + b] != 0.0f) bits2 |= (1u << b);
            smb[256 + t] = bits2;
        }
    }
    __syncthreads();

    unsigned bits_arr[16];
    int cq[8], ck[8];
    #pragma unroll
    for (int s = 0; s < 8; s++) { cq[s] = 0; ck[s] = 0; }

    for (int u = 0; u < 16; u++) {
        int i = t * 16 + u;
        unsigned b = 0;
        #pragma unroll
        for (int p = 0; p < NPHASE; p++)
            b |= ((smb[p * 128 + (i >> 5)] >> (i & 31)) & 1u) << p;
        bits_arr[u] = b;
        cq[b]++;
        #pragma unroll
        for (int s = 1; s < 8; s++)
            if (b & (unsigned)s) ck[s]++;
    }
    #pragma unroll
    for (int s = 0; s < 8; s++) { sq[s][t] = cq[s]; sk[s][t] = ck[s]; }
    __syncthreads();

    // all 15 inclusive scans advanced together: 8 rounds x 2 barriers
    for (int off = 1; off < 256; off <<= 1) {
        int uq[8], uk[7];
        #pragma unroll
        for (int s = 0; s < 8; s++) uq[s] = (t >= off) ? sq[s][t - off] : 0;
        #pragma unroll
        for (int s = 0; s < 7; s++) uk[s] = (t >= off) ? sk[s + 1][t - off] : 0;
        __syncthreads();
        #pragma unroll
        for (int s = 0; s < 8; s++) sq[s][t] += uq[s];
        #pragma unroll
        for (int s = 0; s < 7; s++) sk[s + 1][t] += uk[s];
        __syncthreads();
    }

    // per-sig totals + prefixes: computed redundantly in every thread
    int cnt[8], kc[8], base[8];
    {
        int acc = 0;
        #pragma unroll
        for (int s = 0; s < 8; s++) {
            cnt[s] = sq[s][255];
            base[s] = acc;
            acc += cnt[s];
        }
        #pragma unroll
        for (int s = 1; s < 8; s++) kc[s] = sk[s][255];
    }

    // unit-table prefix: units_s = ceil(cnt_s/QBLK) * ns_s
    int ustart[9];
    int nb[8], ns[8];
    {
        int acc = 0;
        ustart[1] = 0;
        #pragma unroll
        for (int s = 1; s < 8; s++) {
            nb[s] = (cnt[s] + QBLK - 1) / QBLK;
            int tiles = (kc[s] + KTILE - 1) / KTILE;
            ns[s] = (tiles + UT - 1) / UT;
            if (ns[s] < 1) ns[s] = 1;
            ustart[s] = acc;
            acc += nb[s] * ns[s];
        }
        ustart[8] = acc;
    }
    const int nu = ustart[8];

    if (t == 0) {
        #pragma unroll
        for (int s = 0; s < 8; s++) {
            g_grp_off[s] = base[s];
            g_grp_cnt[s] = cnt[s];
        }
        #pragma unroll
        for (int s = 1; s < 8; s++) {
            g_kcnt[s] = kc[s];
            g_nsplit[s] = ns[s];
        }
        g_nunits = nu;
    }

    // parallel unit fill
    for (int u = t; u < nu; u += 256) {
        int s = 1;
        #pragma unroll
        for (int ss = 2; ss < 8; ss++)
            if (u >= ustart[ss]) s = ss;
        int loc = u - ustart[s];
        int b = loc / ns[s];
        int sp = loc - b * ns[s];
        g_u_sig[u] = s;
        g_u_qoff[u] = base[s] + b * QBLK;
        g_u_qend[u] = base[s] + cnt[s];
        g_u_t0[u] = sp * UT * KTILE;
        int t1 = (sp + 1) * UT * KTILE;
        g_u_t1[u] = (t1 < kc[s]) ? t1 : kc[s];
        g_u_spl[u] = sp;
    }

    // pass 2: deterministic placement (index-sorted within each group)
    int qcur[8], kcur[8];
    #pragma unroll
    for (int s = 0; s < 8; s++) {
        qcur[s] = base[s] + sq[s][t] - cq[s];
        kcur[s] = sk[s][t] - ck[s];
    }
    for (int u = 0; u < 16; u++) {
        int i = t * 16 + u;
        unsigned b = bits_arr[u];
        g_qidx[qcur[b]++] = i;
        #pragma unroll
        for (int s = 1; s < 8; s++)
            if (b & (unsigned)s) g_kidx[s][kcur[s]++] = i;
    }
}

// ---------------------------------------------------------------------------
// QKV projection via bf16 split-precision MMA (proven R10 version).
// ---------------------------------------------------------------------------
#define SKA 40
#define SNB 72

__global__ __launch_bounds__(256) void qkv_gemm(
    const float* __restrict__ X,
    const float* __restrict__ Wq, const float* __restrict__ Wk,
    const float* __restrict__ Wv)
{
    const float* W = (blockIdx.z == 0) ? Wq : (blockIdx.z == 1) ? Wk : Wv;
    float* Dst = (blockIdx.z == 0) ? g_q : (blockIdx.z == 1) ? g_k : g_v;

    __shared__ __nv_bfloat16 Ah[128 * SKA], Al[128 * SKA];
    __shared__ __nv_bfloat16 Bh[32 * SNB],  Bl[32 * SNB];

    const int tid  = threadIdx.x;
    const int lane = tid & 31;
    const int wid  = tid >> 5;
    const int warp_m = wid >> 1;
    const int warp_n = wid & 1;
    const int m0 = blockIdx.y * 128;
    const int n0 = blockIdx.x * 64;
    const int quad = lane >> 3, rr = lane & 7;

    float c[2][4][4];
    #pragma unroll
    for (int mf = 0; mf < 2; mf++)
        #pragma unroll
        for (int nf = 0; nf < 4; nf++)
            #pragma unroll
            for (int r = 0; r < 4; r++) c[mf][nf][r] = 0.0f;

    const int arow = tid >> 1, ahalf = (tid & 1) * 16;
    const int brow = tid >> 3, bcol = (tid & 7) * 8;

    unsigned aAh[2], aAl[2];
    #pragma unroll
    for (int mf = 0; mf < 2; mf++) {
        int mrow = warp_m * 32 + mf * 16 + (quad & 1) * 8 + rr;
        int kcol = (quad >> 1) * 8;
        aAh[mf] = s2u(&Ah[mrow * SKA + kcol]);
        aAl[mf] = s2u(&Al[mrow * SKA + kcol]);
    }
    unsigned aBh[2], aBl[2];
    #pragma unroll
    for (int nf2 = 0; nf2 < 2; nf2++) {
        int krow = (quad & 1) * 8 + rr;
        int ncol = warp_n * 32 + nf2 * 16 + (quad >> 1) * 8;
        aBh[nf2] = s2u(&Bh[krow * SNB + ncol]);
        aBl[nf2] = s2u(&Bl[krow * SNB + ncol]);
    }

    for (int k0 = 0; k0 < DMODEL; k0 += 32) {
        float4 av[4], wv[2];
        const float4* asrc = (const float4*)(X + (size_t)(m0 + arow) * DMODEL + k0 + ahalf);
        #pragma unroll
        for (int j = 0; j < 4; j++) av[j] = asrc[j];
        const float4* wsrc = (const float4*)(W + (size_t)(k0 + brow) * DMODEL + n0 + bcol);
        #pragma unroll
        for (int j = 0; j < 2; j++) wv[j] = wsrc[j];
        __syncthreads();

        #pragma unroll
        for (int j = 0; j < 4; j++) {
            float f[4] = {av[j].x, av[j].y, av[j].z, av[j].w};
            #pragma unroll
            for (int e = 0; e < 4; e += 2) {
                __nv_bfloat16 h0 = __float2bfloat16_rn(f[e]);
                __nv_bfloat16 h1 = __float2bfloat16_rn(f[e + 1]);
                __nv_bfloat16 l0 = __float2bfloat16_rn(f[e] - __bfloat162float(h0));
                __nv_bfloat16 l1 = __float2bfloat16_rn(f[e + 1] - __bfloat162float(h1));
                int off = arow * SKA + ahalf + j * 4 + e;
                *(__nv_bfloat162*)&Ah[off] = __nv_bfloat162(h0, h1);
                *(__nv_bfloat162*)&Al[off] = __nv_bfloat162(l0, l1);
            }
        }
        #pragma unroll
        for (int j = 0; j < 2; j++) {
            float f[4] = {wv[j].x, wv[j].y, wv[j].z, wv[j].w};
            #pragma unroll
            for (int e = 0; e < 4; e += 2) {
                __nv_bfloat16 h0 = __float2bfloat16_rn(f[e]);
                __nv_bfloat16 h1 = __float2bfloat16_rn(f[e + 1]);
                __nv_bfloat16 l0 = __float2bfloat16_rn(f[e] - __bfloat162float(h0));
                __nv_bfloat16 l1 = __float2bfloat16_rn(f[e + 1] - __bfloat162float(h1));
                int off = brow * SNB + bcol + j * 4 + e;
                *(__nv_bfloat162*)&Bh[off] = __nv_bfloat162(h0, h1);
                *(__nv_bfloat162*)&Bl[off] = __nv_bfloat162(l0, l1);
            }
        }
        __syncthreads();

        #pragma unroll
        for (int ks = 0; ks < 2; ks++) {
            const unsigned koffA = ks * 16 * 2;
            const unsigned koffB = (unsigned)(ks * 16 * SNB * 2);
            unsigned ah[2][4], al[2][4];
            #pragma unroll
            for (int mf = 0; mf < 2; mf++) {
                LDSM_X4(ah[mf][0], ah[mf][1], ah[mf][2], ah[mf][3], aAh[mf] + koffA);
                LDSM_X4(al[mf][0], al[mf][1], al[mf][2], al[mf][3], aAl[mf] + koffA);
            }
            unsigned bh[4][2], bl[4][2];
            #pragma unroll
            for (int nf2 = 0; nf2 < 2; nf2++) {
                unsigned r0, r1, r2, r3;
                LDSM_X4T(r0, r1, r2, r3, aBh[nf2] + koffB);
                bh[nf2 * 2][0] = r0;  bh[nf2 * 2][1] = r1;
                bh[nf2 * 2 + 1][0] = r2;  bh[nf2 * 2 + 1][1] = r3;
                LDSM_X4T(r0, r1, r2, r3, aBl[nf2] + koffB);
                bl[nf2 * 2][0] = r0;  bl[nf2 * 2][1] = r1;
                bl[nf2 * 2 + 1][0] = r2;  bl[nf2 * 2 + 1][1] = r3;
            }
            #pragma unroll
            for (int mf = 0; mf < 2; mf++)
                #pragma unroll
                for (int nf = 0; nf < 4; nf++) {
                    MMA_BF16(c[mf][nf], ah[mf], bh[nf]);
                    MMA_BF16(c[mf][nf], ah[mf], bl[nf]);
                    MMA_BF16(c[mf][nf], al[mf], bh[nf]);
                }
        }
    }

    #pragma unroll
    for (int mf = 0; mf < 2; mf++) {
        #pragma unroll
        for (int nf = 0; nf < 4; nf++) {
            int row = m0 + warp_m * 32 + mf * 16 + (lane >> 2);
            int col = n0 + warp_n * 32 + nf * 8 + (lane & 3) * 2;
            int h = col / DH, d = col % DH;
            float* base = Dst + (size_t)h * NTOK * DH;
            *(float2*)&base[(size_t)row * DH + d] =
                make_float2(c[mf][nf][0], c[mf][nf][1]);
            *(float2*)&base[(size_t)(row + 8) * DH + d] =
                make_float2(c[mf][nf][2], c[mf][nf][3]);
        }
    }
}

// ---------------------------------------------------------------------------
// Per-head V column mean: stage 1 (proven R11 version); stage 2 folded into
// the attention kernel's dead-block path.
// ---------------------------------------------------------------------------
__global__ __launch_bounds__(320) void meanv1_kernel() {
    __shared__ float red[320];
    const int head = blockIdx.x;
    const int chunk = blockIdx.y;
    const int t = threadIdx.x;
    const int d = t % DH, r = t / DH;
    float s = 0.0f;
    const int j0 = chunk * 256;
    for (int j = j0 + r; j < j0 + 256; j += 8)
        s += g_v[((size_t)head * NTOK + j) * DH + d];
    red[t] = s;
    __syncthreads();
    if (r == 0) {
        float tot = 0.0f;
        #pragma unroll
        for (int rr = 0; rr < 8; rr++) tot += red[rr * DH + d];
        g_mvpart[chunk][head * DH + d] = tot;
    }
}

// ---------------------------------------------------------------------------
// Flash attention (R14 version: direct indirect K/V loads). The dead block
// (x == g_nunits, y == 0) performs the meanv stage-2 reduction — one fewer
// kernel launch. MAXU > nunits always, so that block exists.
// ---------------------------------------------------------------------------
__global__ __launch_bounds__(128) void attn_kernel() {
    if (blockIdx.x >= g_nunits) {
        if (blockIdx.x == g_nunits && blockIdx.y == 0) {
            for (int i = threadIdx.x; i < HEADS * DH; i += 128) {
                float s = 0.0f;
                #pragma unroll
                for (int c = 0; c < 16; c++) s += g_mvpart[c][i];
                g_meanv[i] = s * (1.0f / (float)NTOK);
            }
        }
        return;
    }
    __shared__ __align__(16) float ksh[KTILE * DH];
    __shared__ __align__(16) float vsh[KTILE * DH];

    const int tid  = threadIdx.x;
    const int head = blockIdx.y;
    const int uix  = blockIdx.x;
    const int sig  = g_u_sig[uix];
    const int qoff = g_u_qoff[uix];
    const int qend = g_u_qend[uix];
    const int t_start = g_u_t0[uix];
    const int t_end   = g_u_t1[uix];
    const int spl  = g_u_spl[uix];
    const int q    = tid >> 1;
    const int half = tid & 1;
    const int ql   = qoff + q;
    const bool vq  = ql < qend;
    const int qi   = g_qidx[vq ? ql : qoff];
    const float scale = 0.15811388300841898f * 1.4426950408889634f;

    const float* Kh = g_k + (size_t)head * NTOK * DH;
    const float* Vh = g_v + (size_t)head * NTOK * DH;
    const int* kidx = g_kidx[sig];

    ull q2[10];
    {
        const float4* qp = (const float4*)(g_q + ((size_t)head * NTOK + qi) * DH + half * 20);
        #pragma unroll
        for (int i = 0; i < 5; i++) {
            float4 v = qp[i];
            PACK2(q2[2 * i + 0], v.x * scale, v.y * scale);
            PACK2(q2[2 * i + 1], v.z * scale, v.w * scale);
        }
    }

    float m = -FLT_MAX, l = 0.0f;
    ull acc2[10];
    #pragma unroll
    for (int d = 0; d < 10; d++) acc2[d] = 0ull;

    for (int t0 = t_start; t0 < t_end; t0 += KTILE) {
        __syncthreads();
        float4* ks4 = (float4*)ksh;
        float4* vs4 = (float4*)vsh;
        #pragma unroll
        for (int i = tid; i < KTILE * 10; i += 128) {
            int row = i / 10, c4 = i % 10;
            int gr = t0 + row;
            int idx = (gr < t_end) ? kidx[gr] : 0;
            size_t src = (size_t)idx * DH + c4 * 4;
            ks4[i] = *(const float4*)(Kh + src);
            vs4[i] = *(const float4*)(Vh + src);
        }
        __syncthreads();

        const int lim = (t_end - t0 < KTILE) ? (t_end - t0) : KTILE;
        for (int c = 0; c < lim; c += 16) {
            float s[16];
            float cmax = -FLT_MAX;
            #pragma unroll
            for (int j = 0; j < 16; j++) {
                const ulonglong2* kr =
                    (const ulonglong2*)(ksh + (c + j) * DH + half * 20);
                ull sva = 0ull, svb = 0ull;
                ulonglong2 k0 = kr[0], k1 = kr[1], k2 = kr[2], k3 = kr[3], k4 = kr[4];
                FMA2(sva, q2[0], k0.x, sva);
                FMA2(svb, q2[1], k0.y, svb);
                FMA2(sva, q2[2], k1.x, sva);
                FMA2(svb, q2[3], k1.y, svb);
                FMA2(sva, q2[4], k2.x, sva);
                FMA2(svb, q2[5], k2.y, svb);
                FMA2(sva, q2[6], k3.x, sva);
                FMA2(svb, q2[7], k3.y, svb);
                FMA2(sva, q2[8], k4.x, sva);
                FMA2(svb, q2[9], k4.y, svb);
                float la, ha, lb, hb;
                UNPACK2(la, ha, sva);
                UNPACK2(lb, hb, svb);
                float svf = (la + ha) + (lb + hb);
                svf += __shfl_xor_sync(0xffffffffu, svf, 1);
                s[j] = (c + j < lim) ? svf : -FLT_MAX;
                cmax = fmaxf(cmax, s[j]);
            }
            float mnew = fmaxf(m, cmax);
            float corr = ex2(m - mnew);
            l *= corr;
            {
                ull corr2;
                PACK2(corr2, corr, corr);
                #pragma unroll
                for (int d = 0; d < 10; d++) MUL2(acc2[d], acc2[d], corr2);
            }
            #pragma unroll
            for (int j = 0; j < 16; j++) {
                float pj = ex2(s[j] - mnew);
                l += pj;
                ull pj2;
                PACK2(pj2, pj, pj);
                const ulonglong2* vr =
                    (const ulonglong2*)(vsh + (c + j) * DH + half * 20);
                ulonglong2 v0 = vr[0], v1 = vr[1], v2 = vr[2], v3 = vr[3], v4 = vr[4];
                FMA2(acc2[0], pj2, v0.x, acc2[0]);
                FMA2(acc2[1], pj2, v0.y, acc2[1]);
                FMA2(acc2[2], pj2, v1.x, acc2[2]);
                FMA2(acc2[3], pj2, v1.y, acc2[3]);
                FMA2(acc2[4], pj2, v2.x, acc2[4]);
                FMA2(acc2[5], pj2, v2.y, acc2[5]);
                FMA2(acc2[6], pj2, v3.x, acc2[6]);
                FMA2(acc2[7], pj2, v3.y, acc2[7]);
                FMA2(acc2[8], pj2, v4.x, acc2[8]);
                FMA2(acc2[9], pj2, v4.y, acc2[9]);
            }
            m = mnew;
        }
    }

    if (vq) {
        size_t base = (size_t)(spl * HEADS + head) * NTOK + ql;
        if (half == 0) {
            g_pm[base] = m;
            g_pl[base] = l;
        }
        float4* pp = (float4*)(g_pacc + base * DH + half * 20);
        #pragma unroll
        for (int d4 = 0; d4 < 5; d4++) {
            float4 r;
            UNPACK2(r.x, r.y, acc2[2 * d4 + 0]);
            UNPACK2(r.z, r.w, acc2[2 * d4 + 1]);
            pp[d4] = r;
        }
    }
}

// ---------------------------------------------------------------------------
// Merge split partials + meanV fill (fused; proven R10 version)
// ---------------------------------------------------------------------------
__global__ __launch_bounds__(256) void reduce_kernel() {
    const int idx = blockIdx.x * 256 + threadIdx.x;
    if (idx >= NTOK * HEADS) return;
    const int ql = idx / HEADS;
    const int head = idx % HEADS;
    const int nq0 = g_grp_cnt[0];
    const int qi = g_qidx[ql];
    float* op = g_o + (size_t)qi * DMODEL + head * DH;

    if (ql < nq0) {
        const float4* mv = (const float4*)(g_meanv + head * DH);
        #pragma unroll
        for (int d4 = 0; d4 < 10; d4++) *(float4*)(op + d4 * 4) = mv[d4];
        return;
    }

    int sig = 1;
    #pragma unroll
    for (int s = 2; s < 8; s++)
        if (ql >= g_grp_off[s]) sig = s;
    const int ns = g_nsplit[sig];

    float m = -FLT_MAX;
    for (int s = 0; s < ns; s++) {
        float ms = g_pm[(size_t)(s * HEADS + head) * NTOK + ql];
        m = fmaxf(m, ms);
    }
    float l = 0.0f;
    for (int s = 0; s < ns; s++) {
        size_t base = (size_t)(s * HEADS + head) * NTOK + ql;
        l += g_pl[base] * ex2(g_pm[base] - m);
    }
    const float inv = 1.0f / l;

    float sum[DH];
    #pragma unroll
    for (int d = 0; d < DH; d++) sum[d] = 0.0f;
    for (int s = 0; s < ns; s++) {
        size_t base = (size_t)(s * HEADS + head) * NTOK + ql;
        float w = ex2(g_pm[base] - m);
        const float4* pa = (const float4*)(g_pacc + base * DH);
        #pragma unroll
        for (int d4 = 0; d4 < 10; d4++) {
            float4 a = pa[d4];
            sum[d4 * 4 + 0] += w * a.x;
            sum[d4 * 4 + 1] += w * a.y;
            sum[d4 * 4 + 2] += w * a.z;
            sum[d4 * 4 + 3] += w * a.w;
        }
    }
    #pragma unroll
    for (int d4 = 0; d4 < 10; d4++) {
        float4 r;
        r.x = sum[d4 * 4 + 0] * inv;
        r.y = sum[d4 * 4 + 1] * inv;
        r.z = sum[d4 * 4 + 2] * inv;
        r.w = sum[d4 * 4 + 3] * inv;
        *(float4*)(op + d4 * 4) = r;
    }
}

// ---------------------------------------------------------------------------
// Output projection via bf16 split MMA (proven R11 version).
// ---------------------------------------------------------------------------
__global__ __launch_bounds__(256) void out_gemm(
    const float* __restrict__ Wo, const float* __restrict__ bo,
    float* __restrict__ out)
{
    __shared__ __nv_bfloat16 Ah[128 * SKA], Al[128 * SKA];
    __shared__ __nv_bfloat16 Bh[32 * SNB],  Bl[32 * SNB];

    const int tid  = threadIdx.x;
    const int lane = tid & 31;
    const int wid  = tid >> 5;
    const int warp_m = wid >> 1;
    const int warp_n = wid & 1;
    const int m0 = blockIdx.y * 128;
    const int n0 = blockIdx.x * 64;
    const int quad = lane >> 3, rr = lane & 7;

    float c[2][4][4];
    #pragma unroll
    for (int mf = 0; mf < 2; mf++)
        #pragma unroll
        for (int nf = 0; nf < 4; nf++)
            #pragma unroll
            for (int r = 0; r < 4; r++) c[mf][nf][r] = 0.0f;

    const int arow = tid >> 1, ahalf = (tid & 1) * 16;
    const int brow = tid >> 3, bcol = (tid & 7) * 8;

    unsigned aAh[2], aAl[2];
    #pragma unroll
    for (int mf = 0; mf < 2; mf++) {
        int mrow = warp_m * 32 + mf * 16 + (quad & 1) * 8 + rr;
        int kcol = (quad >> 1) * 8;
        aAh[mf] = s2u(&Ah[mrow * SKA + kcol]);
        aAl[mf] = s2u(&Al[mrow * SKA + kcol]);
    }
    unsigned aBh[2], aBl[2];
    #pragma unroll
    for (int nf2 = 0; nf2 < 2; nf2++) {
        int krow = (quad & 1) * 8 + rr;
        int ncol = warp_n * 32 + nf2 * 16 + (quad >> 1) * 8;
        aBh[nf2] = s2u(&Bh[krow * SNB + ncol]);
        aBl[nf2] = s2u(&Bl[krow * SNB + ncol]);
    }

    for (int k0 = 0; k0 < DMODEL; k0 += 32) {
        float4 av[4], wv[2];
        const float4* asrc = (const float4*)(g_o + (size_t)(m0 + arow) * DMODEL + k0 + ahalf);
        #pragma unroll
        for (int j = 0; j < 4; j++) av[j] = asrc[j];
        const float4* wsrc = (const float4*)(Wo + (size_t)(k0 + brow) * DMODEL + n0 + bcol);
        #pragma unroll
        for (int j = 0; j < 2; j++) wv[j] = wsrc[j];
        __syncthreads();

        #pragma unroll
        for (int j = 0; j < 4; j++) {
            float f[4] = {av[j].x, av[j].y, av[j].z, av[j].w};
            #pragma unroll
            for (int e = 0; e < 4; e += 2) {
                __nv_bfloat16 h0 = __float2bfloat16_rn(f[e]);
                __nv_bfloat16 h1 = __float2bfloat16_rn(f[e + 1]);
                __nv_bfloat16 l0 = __float2bfloat16_rn(f[e] - __bfloat162float(h0));
                __nv_bfloat16 l1 = __float2bfloat16_rn(f[e + 1] - __bfloat162float(h1));
                int off = arow * SKA + ahalf + j * 4 + e;
                *(__nv_bfloat162*)&Ah[off] = __nv_bfloat162(h0, h1);
                *(__nv_bfloat162*)&Al[off] = __nv_bfloat162(l0, l1);
            }
        }
        #pragma unroll
        for (int j = 0; j < 2; j++) {
            float f[4] = {wv[j].x, wv[j].y, wv[j].z, wv[j].w};
            #pragma unroll
            for (int e = 0; e < 4; e += 2) {
                __nv_bfloat16 h0 = __float2bfloat16_rn(f[e]);
                __nv_bfloat16 h1 = __float2bfloat16_rn(f[e + 1]);
                __nv_bfloat16 l0 = __float2bfloat16_rn(f[e] - __bfloat162float(h0));
                __nv_bfloat16 l1 = __float2bfloat16_rn(f[e + 1] - __bfloat162float(h1));
                int off = brow * SNB + bcol + j * 4 + e;
                *(__nv_bfloat162*)&Bh[off] = __nv_bfloat162(h0, h1);
                *(__nv_bfloat162*)&Bl[off] = __nv_bfloat162(l0, l1);
            }
        }
        __syncthreads();

        #pragma unroll
        for (int ks = 0; ks < 2; ks++) {
            const unsigned koffA = ks * 16 * 2;
            const unsigned koffB = (unsigned)(ks * 16 * SNB * 2);
            unsigned ah[2][4], al[2][4];
            #pragma unroll
            for (int mf = 0; mf < 2; mf++) {
                LDSM_X4(ah[mf][0], ah[mf][1], ah[mf][2], ah[mf][3], aAh[mf] + koffA);
                LDSM_X4(al[mf][0], al[mf][1], al[mf][2], al[mf][3], aAl[mf] + koffA);
            }
            unsigned bh[4][2], bl[4][2];
            #pragma unroll
            for (int nf2 = 0; nf2 < 2; nf2++) {
                unsigned r0, r1, r2, r3;
                LDSM_X4T(r0, r1, r2, r3, aBh[nf2] + koffB);
                bh[nf2 * 2][0] = r0;  bh[nf2 * 2][1] = r1;
                bh[nf2 * 2 + 1][0] = r2;  bh[nf2 * 2 + 1][1] = r3;
                LDSM_X4T(r0, r1, r2, r3, aBl[nf2] + koffB);
                bl[nf2 * 2][0] = r0;  bl[nf2 * 2][1] = r1;
                bl[nf2 * 2 + 1][0] = r2;  bl[nf2 * 2 + 1][1] = r3;
            }
            #pragma unroll
            for (int mf = 0; mf < 2; mf++)
                #pragma unroll
                for (int nf = 0; nf < 4; nf++) {
                    MMA_BF16(c[mf][nf], ah[mf], bh[nf]);
                    MMA_BF16(c[mf][nf], ah[mf], bl[nf]);
                    MMA_BF16(c[mf][nf], al[mf], bh[nf]);
                }
        }
    }

    #pragma unroll
    for (int mf = 0; mf < 2; mf++) {
        #pragma unroll
        for (int nf = 0; nf < 4; nf++) {
            int row = m0 + warp_m * 32 + mf * 16 + (lane >> 2);
            int col = n0 + warp_n * 32 + nf * 8 + (lane & 3) * 2;
            float2 b = *(const float2*)(bo + col);
            *(float2*)&out[(size_t)row * DMODEL + col] =
                make_float2(c[mf][nf][0] + b.x, c[mf][nf][1] + b.y);
            *(float2*)&out[(size_t)(row + 8) * DMODEL + col] =
                make_float2(c[mf][nf][2] + b.x, c[mf][nf][3] + b.y);
        }
    }
}

// ---------------------------------------------------------------------------
extern "C" void kernel_launch(void* const* d_in, const int* in_sizes, int n_in,
                              void* d_out, int out_size)
{
    const float* x  = (const float*)d_in[0];
    const float* gm = (const float*)d_in[1];
    const float* Wq = (const float*)d_in[2];
    const float* Wk = (const float*)d_in[3];
    const float* Wv = (const float*)d_in[4];
    const float* Wo = (const float*)d_in[5];
    const float* bo = (const float*)d_in[6];
    float* out = (float*)d_out;

    plan_kernel<<<1, 256>>>(gm);

    dim3 gq(DMODEL / 64, NTOK / 128, 3);
    qkv_gemm<<<gq, 256>>>(x, Wq, Wk, Wv);

    dim3 gm1(HEADS, 16);
    meanv1_kernel<<<gm1, 320>>>();

    dim3 ga(MAXU, HEADS);
    attn_kernel<<<ga, 128>>>();

    reduce_kernel<<<(NTOK * HEADS + 255) / 256, 256>>>();

    dim3 go(DMODEL / 64, NTOK / 128);
    out_gemm<<<go, 256>>>(Wo, bo, out);
}